// round 9
// baseline (speedup 1.0000x reference)
#include <cuda_runtime.h>

#define NN 10000
#define EE 160000
#define EPS 1e-5f
#define ELLW 64
#define CEILDIV(a,b) (((a)+(b)-1)/(b))

// ---------------- scratch (static device globals; no allocation) ----------------
__device__ __align__(16) float g_deg[NN];
__device__ __align__(16) int   g_cnt[NN];
__device__ __align__(16) int   g_ell_src[NN * ELLW];
__device__ __align__(16) float g_ell_w[NN * ELLW];
__device__ __align__(16) float g_y1[NN * 512];
__device__ __align__(16) float g_t1[NN * 512];
__device__ __align__(16) float g_y2[NN * 256];
__device__ __align__(16) float g_p2[NN * 256];
__device__ __align__(16) float g_tx2[NN * 256];
__device__ __align__(16) float g_y3[NN * 128];
__device__ __align__(16) float g_sums[896];
__device__ __align__(16) float g_ssqs[896];
__device__ __align__(16) float g_bnsc[896];
__device__ __align__(16) float g_bnsh[896];

__device__ __forceinline__ float* buf(int id) {
    switch (id) {
        case 1: return g_y1;
        case 2: return g_t1;
        case 3: return g_y2;
        case 4: return g_p2;
        case 5: return g_tx2;
        case 6: return g_y3;
    }
    return nullptr;
}

// ---------------- graph build (ELL by dst) ----------------
__global__ void k_init_graph() {
    int i = blockIdx.x * blockDim.x + threadIdx.x;
    if (i < NN) { g_deg[i] = 0.0f; g_cnt[i] = 0; }
    if (i < 896) { g_sums[i] = 0.0f; g_ssqs[i] = 0.0f; }
}
__global__ void k_deg(const int* __restrict__ ei, const float* __restrict__ ea) {
    int e = blockIdx.x * blockDim.x + threadIdx.x;
    if (e >= EE) return;
    atomicAdd(&g_deg[ei[e]], ea[e]);
}
__global__ void k_norm_push(const int* __restrict__ ei, const float* __restrict__ ea) {
    int e = blockIdx.x * blockDim.x + threadIdx.x;
    if (e >= EE) return;
    int s = ei[e];
    int d = ei[EE + e];
    float ds = g_deg[s], dd = g_deg[d];
    float is = (ds > 0.0f) ? rsqrtf(ds) : 0.0f;
    float id = (dd > 0.0f) ? rsqrtf(dd) : 0.0f;
    float w = -is * ea[e] * id;
    int pos = atomicAdd(&g_cnt[d], 1);
    g_ell_src[d * ELLW + pos] = s;
    g_ell_w[d * ELLW + pos] = w;
}

// ---------------- BN coefficients ----------------
__global__ void k_bn_coef(const float* __restrict__ gamma, const float* __restrict__ beta,
                          int n, int F, int soff) {
    int f = threadIdx.x;
    if (f >= F) return;
    float inv_n = 1.0f / (float)n;
    float mu = g_sums[soff + f] * inv_n;
    float var = g_ssqs[soff + f] * inv_n - mu * mu;
    float sc = gamma[f] * rsqrtf(var + EPS);
    g_bnsc[soff + f] = sc;
    g_bnsh[soff + f] = beta[f] - mu * sc;
}

// ---------------- tf32 GEMM: BM=64, BN=128, BKT=16, fragment-major A AND B smem ----------------
#define BMT 64
#define BNT 128
#define BKT 16
#define NF 4
#define A_STAGE (2 * NF * 128)   // 1024 floats
#define B_STAGE 2048             // 2 kh * 4 g * 2 reg * 128 floats

__device__ __forceinline__ unsigned f2tf(float x) {
    unsigned u;
    asm("cvt.rna.tf32.f32 %0, %1;" : "=r"(u) : "f"(x));
    return u;
}
__device__ __forceinline__ unsigned fui(float x) { return __float_as_uint(x); }

__global__ __launch_bounds__(256, 4) void gemm_tf32(
    const float* __restrict__ Aext, int aid0, int aid1, int aid2,
    const float* __restrict__ B0, const float* __restrict__ B1, const float* __restrict__ B2,
    const float* __restrict__ bias, int Cid,
    int M, int N, int Kseg, int segs, int soff,
    int coff0, int coff1, int coff2)
{
    __shared__ __align__(16) float As[2][A_STAGE];
    __shared__ __align__(16) float Bsf[2][B_STAGE];

    const float* Ap[3];
    Ap[0] = Aext ? Aext : buf(aid0);
    Ap[1] = buf(aid1);
    Ap[2] = buf(aid2);
    const float* Bp[3] = {B0, B1, B2};
    float* C = buf(Cid);

    const int tid = threadIdx.x;
    const int lane = tid & 31;
    const int warp = tid >> 5;
    const int qr = lane >> 2;
    const int qc = lane & 3;
    const int wm = (warp & 1) * 32;
    const int ms0 = (warp & 1) * 2;
    const int wn = (warp >> 1) * 32;

    const int row0 = blockIdx.y * BMT;
    const int col0 = blockIdx.x * BNT;

    // ---- A loader (unchanged from R8): one float4 per thread ----
    const int arow = tid >> 2;
    const int ak = (tid & 3) << 2;
    const bool avalid = (row0 + arow) < M;
    const int wr = arow & 15;
    const int wms = arow >> 4;
    const int wkh = ak >> 3;
    const int wkb = (ak >> 2) & 1;
    const int xsw = ((wr >> 1) & 3) << 2;
    const int awbase = (wkh * NF + wms) * 128 + ((wr & 7) << 4) + (wr >> 3) + (wkb << 1);

    // A fragment read base
    const int rpos = (qr << 2) + (qc ^ ((qr >> 1) & 3));
    const int ardbase = ms0 * 128 + (rpos << 2);

    // ---- B loader: rows brow(+8), cols bcol..bcol+3 -> fragment pages ----
    const int brow = tid >> 5;                  // 0..7 (it adds 8)
    const int bcol = (tid & 31) << 2;
    const int bg = bcol >> 5;                   // n-group
    const int bj = (bcol >> 3) & 3;             // j
    const int bqr0 = bcol & 7;                  // base qr (0 or 4)
    const int breg = brow >> 2;
    const int bqc = brow & 3;
    // pos(i, it) = it*1024 + bg*256 + breg*128 + (4*(bqr0+i)+bqc)*4 + bj
    const int bwbase = bg * 256 + breg * 128 + (4 * bqr0 + bqc) * 4 + bj;

    // B fragment read base: page at kh*1024 + g*256 (+reg*128), lane slot*4
    const int brdbase = (warp >> 1) * 256 + lane * 4;

    float acc[2][4][4];
#pragma unroll
    for (int i = 0; i < 2; i++)
#pragma unroll
        for (int j = 0; j < 4; j++)
#pragma unroll
            for (int e = 0; e < 4; e++) acc[i][j][e] = 0.0f;

    const int K = Kseg * segs;

    float4 rA, rB[2];
    auto fetch = [&](int k0) {
        const int seg = k0 / Kseg;
        const int kloc = k0 - seg * Kseg;
        const int coff = (seg == 0) ? coff0 : (seg == 1) ? coff1 : coff2;
        const float* A = Ap[seg];
        const float* B = Bp[seg];
        rA = make_float4(0.f, 0.f, 0.f, 0.f);
        if (avalid) rA = *(const float4*)(A + (size_t)(row0 + arow) * Kseg + kloc + ak);
        if (coff >= 0) {
            float4 sc = *(const float4*)(g_bnsc + coff + kloc + ak);
            float4 sh = *(const float4*)(g_bnsh + coff + kloc + ak);
            rA.x = fmaxf(fmaf(rA.x, sc.x, sh.x), 0.f);
            rA.y = fmaxf(fmaf(rA.y, sc.y, sh.y), 0.f);
            rA.z = fmaxf(fmaf(rA.z, sc.z, sh.z), 0.f);
            rA.w = fmaxf(fmaf(rA.w, sc.w, sh.w), 0.f);
        }
#pragma unroll
        for (int it = 0; it < 2; it++)
            rB[it] = *(const float4*)(B + (size_t)(kloc + brow + it * 8) * N + col0 + bcol);
    };
    auto commit = [&](int s) {
        float* Aw = As[s];
        Aw[awbase + ((0 << 2) ^ xsw)] = __uint_as_float(f2tf(rA.x));
        Aw[awbase + ((1 << 2) ^ xsw)] = __uint_as_float(f2tf(rA.y));
        Aw[awbase + ((2 << 2) ^ xsw)] = __uint_as_float(f2tf(rA.z));
        Aw[awbase + ((3 << 2) ^ xsw)] = __uint_as_float(f2tf(rA.w));
        float* Bw = Bsf[s];
#pragma unroll
        for (int it = 0; it < 2; it++) {
            float* p = Bw + it * 1024 + bwbase;
            p[0]  = __uint_as_float(f2tf(rB[it].x));
            p[16] = __uint_as_float(f2tf(rB[it].y));
            p[32] = __uint_as_float(f2tf(rB[it].z));
            p[48] = __uint_as_float(f2tf(rB[it].w));
        }
    };

    fetch(0);
    commit(0);
    __syncthreads();

    int cur = 0;
    for (int k0 = 0; k0 < K; k0 += BKT, cur ^= 1) {
        const bool hasNext = (k0 + BKT) < K;
        if (hasNext) fetch(k0 + BKT);

        const float* Ac = As[cur];
        const float* Bc = Bsf[cur];
#pragma unroll
        for (int kh = 0; kh < 2; kh++) {
            const float* Af = Ac + kh * (NF * 128) + ardbase;
            float4 fa0 = *(const float4*)(Af);
            float4 fa1 = *(const float4*)(Af + 128);
            const float* Bf = Bc + kh * 1024 + brdbase;
            float4 qb0 = *(const float4*)(Bf);          // b0 regs, j=0..3
            float4 qb1 = *(const float4*)(Bf + 128);    // b1 regs, j=0..3
            const unsigned b0a[4] = {fui(qb0.x), fui(qb0.y), fui(qb0.z), fui(qb0.w)};
            const unsigned b1a[4] = {fui(qb1.x), fui(qb1.y), fui(qb1.z), fui(qb1.w)};
#pragma unroll
            for (int j = 0; j < 4; j++) {
                asm volatile(
                    "mma.sync.aligned.m16n8k8.row.col.f32.tf32.tf32.f32 "
                    "{%0,%1,%2,%3}, {%4,%5,%6,%7}, {%8,%9}, {%0,%1,%2,%3};"
                    : "+f"(acc[0][j][0]), "+f"(acc[0][j][1]),
                      "+f"(acc[0][j][2]), "+f"(acc[0][j][3])
                    : "r"(fui(fa0.x)), "r"(fui(fa0.y)), "r"(fui(fa0.z)), "r"(fui(fa0.w)),
                      "r"(b0a[j]), "r"(b1a[j]));
                asm volatile(
                    "mma.sync.aligned.m16n8k8.row.col.f32.tf32.tf32.f32 "
                    "{%0,%1,%2,%3}, {%4,%5,%6,%7}, {%8,%9}, {%0,%1,%2,%3};"
                    : "+f"(acc[1][j][0]), "+f"(acc[1][j][1]),
                      "+f"(acc[1][j][2]), "+f"(acc[1][j][3])
                    : "r"(fui(fa1.x)), "r"(fui(fa1.y)), "r"(fui(fa1.z)), "r"(fui(fa1.w)),
                      "r"(b0a[j]), "r"(b1a[j]));
            }
        }

        if (hasNext) commit(cur ^ 1);
        __syncthreads();
    }

    // ---- epilogue: bias add, store raw, fused BN stats ----
#pragma unroll
    for (int j = 0; j < 4; j++) {
        int c = col0 + wn + 8 * j + 2 * qc;
        float bx = bias[c], by = bias[c + 1];
#pragma unroll
        for (int i = 0; i < 2; i++) {
            acc[i][j][0] += bx; acc[i][j][1] += by;
            acc[i][j][2] += bx; acc[i][j][3] += by;
        }
    }
#pragma unroll
    for (int i = 0; i < 2; i++) {
        int r = row0 + wm + 16 * i + qr;
#pragma unroll
        for (int j = 0; j < 4; j++) {
            int c = col0 + wn + 8 * j + 2 * qc;
            if (r < M)
                *(float2*)(C + (size_t)r * N + c) = make_float2(acc[i][j][0], acc[i][j][1]);
            if (r + 8 < M)
                *(float2*)(C + (size_t)(r + 8) * N + c) = make_float2(acc[i][j][2], acc[i][j][3]);
        }
    }
#pragma unroll
    for (int j = 0; j < 4; j++) {
        float s0 = 0.f, q0 = 0.f, s1 = 0.f, q1 = 0.f;
#pragma unroll
        for (int i = 0; i < 2; i++) {
            int r = row0 + wm + 16 * i + qr;
            if (r < M) {
                s0 += acc[i][j][0]; q0 += acc[i][j][0] * acc[i][j][0];
                s1 += acc[i][j][1]; q1 += acc[i][j][1] * acc[i][j][1];
            }
            if (r + 8 < M) {
                s0 += acc[i][j][2]; q0 += acc[i][j][2] * acc[i][j][2];
                s1 += acc[i][j][3]; q1 += acc[i][j][3] * acc[i][j][3];
            }
        }
#pragma unroll
        for (int off = 4; off < 32; off <<= 1) {
            s0 += __shfl_xor_sync(0xffffffff, s0, off);
            q0 += __shfl_xor_sync(0xffffffff, q0, off);
            s1 += __shfl_xor_sync(0xffffffff, s1, off);
            q1 += __shfl_xor_sync(0xffffffff, q1, off);
        }
        if (qr == 0) {
            int c = col0 + wn + 8 * j + 2 * qc;
            atomicAdd(&g_sums[soff + c], s0);
            atomicAdd(&g_ssqs[soff + c], q0);
            atomicAdd(&g_sums[soff + c + 1], s1);
            atomicAdd(&g_ssqs[soff + c + 1], q1);
        }
    }
}

// ---------------- propagation (ELL by dst; BN+ReLU applied to gathered h) ----------------
__global__ void k_prop(int hid, int outid, int F, int coff) {
    const float* h = buf(hid);
    float* out = buf(outid);
    int node = blockIdx.x;
    int t = threadIdx.x;
    int cnt = g_cnt[node];
    int base = node * ELLW;
    float4 sc = make_float4(1.f, 1.f, 1.f, 1.f), sh = make_float4(0.f, 0.f, 0.f, 0.f);
    bool useC = coff >= 0;
    if (useC) {
        sc = *(const float4*)(g_bnsc + coff + t * 4);
        sh = *(const float4*)(g_bnsh + coff + t * 4);
    }
    float4 acc = make_float4(0.f, 0.f, 0.f, 0.f);
    for (int e = 0; e < cnt; e++) {
        int s = g_ell_src[base + e];
        float w = g_ell_w[base + e];
        float4 v = *(const float4*)(h + (size_t)s * F + t * 4);
        if (useC) {
            v.x = fmaxf(fmaf(v.x, sc.x, sh.x), 0.f);
            v.y = fmaxf(fmaf(v.y, sc.y, sh.y), 0.f);
            v.z = fmaxf(fmaf(v.z, sc.z, sh.z), 0.f);
            v.w = fmaxf(fmaf(v.w, sc.w, sh.w), 0.f);
        }
        acc.x += w * v.x; acc.y += w * v.y; acc.z += w * v.z; acc.w += w * v.w;
    }
    *(float4*)(out + (size_t)node * F + t * 4) = acc;
}

__global__ void k_prop_cheb(int hid, int subid, int outid, int F, int subcoff) {
    const float* h = buf(hid);
    const float* sub = buf(subid);
    float* out = buf(outid);
    int node = blockIdx.x;
    int t = threadIdx.x;
    int cnt = g_cnt[node];
    int base = node * ELLW;
    float4 acc = make_float4(0.f, 0.f, 0.f, 0.f);
    for (int e = 0; e < cnt; e++) {
        int s = g_ell_src[base + e];
        float w = g_ell_w[base + e];
        float4 v = *(const float4*)(h + (size_t)s * F + t * 4);
        acc.x += w * v.x; acc.y += w * v.y; acc.z += w * v.z; acc.w += w * v.w;
    }
    float4 sc = *(const float4*)(g_bnsc + subcoff + t * 4);
    float4 sh = *(const float4*)(g_bnsh + subcoff + t * 4);
    float4 sv = *(const float4*)(sub + (size_t)node * F + t * 4);
    sv.x = fmaxf(fmaf(sv.x, sc.x, sh.x), 0.f);
    sv.y = fmaxf(fmaf(sv.y, sc.y, sh.y), 0.f);
    sv.z = fmaxf(fmaf(sv.z, sc.z, sh.z), 0.f);
    sv.w = fmaxf(fmaf(sv.w, sc.w, sh.w), 0.f);
    float4 r;
    r.x = 2.0f * acc.x - sv.x;
    r.y = 2.0f * acc.y - sv.y;
    r.z = 2.0f * acc.z - sv.z;
    r.w = 2.0f * acc.w - sv.w;
    *(float4*)(out + (size_t)node * F + t * 4) = r;
}

// ---------------- fc (bn3 on load; 128 -> 6) + log_softmax ----------------
__global__ void k_fc(const float* __restrict__ W,
                     const float* __restrict__ bias, float* __restrict__ out, int n) {
    const float* h = g_y3;
    int gtid = blockIdx.x * blockDim.x + threadIdx.x;
    int node = gtid >> 5;
    int lane = gtid & 31;
    if (node >= n) return;
    float hv[4];
#pragma unroll
    for (int k = 0; k < 4; k++) {
        int col = lane + 32 * k;
        float raw = h[(size_t)node * 128 + col];
        hv[k] = fmaf(raw, g_bnsc[768 + col], g_bnsh[768 + col]);
    }
    float logit[6];
#pragma unroll
    for (int j = 0; j < 6; j++) {
        float s = 0.0f;
#pragma unroll
        for (int k = 0; k < 4; k++) s += hv[k] * W[(lane + 32 * k) * 6 + j];
#pragma unroll
        for (int o = 16; o > 0; o >>= 1) s += __shfl_xor_sync(0xffffffff, s, o);
        logit[j] = s + bias[j];
    }
    if (lane == 0) {
        float mx = logit[0];
#pragma unroll
        for (int j = 1; j < 6; j++) mx = fmaxf(mx, logit[j]);
        float se = 0.0f;
#pragma unroll
        for (int j = 0; j < 6; j++) se += expf(logit[j] - mx);
        float lse = mx + logf(se);
#pragma unroll
        for (int j = 0; j < 6; j++) out[(size_t)node * 6 + j] = logit[j] - lse;
    }
}

// ---------------- launch ----------------
extern "C" void kernel_launch(void* const* d_in, const int* in_sizes, int n_in,
                              void* d_out, int out_size) {
    const float* x    = (const float*)d_in[0];
    const int*   ei   = (const int*)d_in[1];
    const float* ea   = (const float*)d_in[2];
    const float* W1_0 = (const float*)d_in[3];
    const float* b1   = (const float*)d_in[4];
    const float* g1   = (const float*)d_in[5];
    const float* be1  = (const float*)d_in[6];
    const float* W2_0 = (const float*)d_in[7];
    const float* W2_1 = (const float*)d_in[8];
    const float* b2   = (const float*)d_in[9];
    const float* g2   = (const float*)d_in[10];
    const float* be2  = (const float*)d_in[11];
    const float* W3_0 = (const float*)d_in[12];
    const float* W3_1 = (const float*)d_in[13];
    const float* W3_2 = (const float*)d_in[14];
    const float* b3   = (const float*)d_in[15];
    const float* g3   = (const float*)d_in[16];
    const float* be3  = (const float*)d_in[17];
    const float* fcW  = (const float*)d_in[18];
    const float* fcb  = (const float*)d_in[19];
    float* out = (float*)d_out;

    // ---- graph normalization + ELL build ----
    k_init_graph<<<CEILDIV(NN, 256), 256>>>();
    k_deg<<<CEILDIV(EE, 256), 256>>>(ei, ea);
    k_norm_push<<<CEILDIV(EE, 256), 256>>>(ei, ea);

    const int GY = CEILDIV(NN, BMT);   // 157

    // ---- layer 1 ----
    gemm_tf32<<<dim3(512 / BNT, GY), 256>>>(
        x, 0, 0, 0, W1_0, nullptr, nullptr, b1, 1, NN, 512, 768, 1, 0, -1, -1, -1);
    k_bn_coef<<<1, 512>>>(g1, be1, NN, 512, 0);

    // ---- layer 2 ----
    k_prop<<<NN, 128>>>(1, 2, 512, 0);
    gemm_tf32<<<dim3(256 / BNT, GY), 256>>>(
        nullptr, 1, 2, 0, W2_0, W2_1, nullptr, b2, 3, NN, 256, 512, 2, 512, 0, -1, -1);
    k_bn_coef<<<1, 256>>>(g2, be2, NN, 256, 512);

    // ---- layer 3 ----
    k_prop<<<NN, 64>>>(3, 4, 256, 512);
    k_prop_cheb<<<NN, 64>>>(4, 3, 5, 256, 512);
    gemm_tf32<<<dim3(128 / BNT, GY), 256>>>(
        nullptr, 3, 4, 5, W3_0, W3_1, W3_2, b3, 6, NN, 128, 256, 3, 768, 512, -1, -1);
    k_bn_coef<<<1, 128>>>(g3, be3, NN, 128, 768);

    // ---- fc (bn3 fused) + log_softmax ----
    k_fc<<<CEILDIV(NN * 32, 256), 256>>>(fcW, fcb, out, NN);
}

// round 10
// speedup vs baseline: 1.1248x; 1.1248x over previous
#include <cuda_runtime.h>

#define NN 10000
#define EE 160000
#define EPS 1e-5f
#define ELLW 64
#define CEILDIV(a,b) (((a)+(b)-1)/(b))

// ---------------- scratch (static device globals; no allocation) ----------------
__device__ __align__(16) float g_deg[NN];
__device__ __align__(16) int   g_cnt[NN];
__device__ __align__(16) int   g_ell_src[NN * ELLW];
__device__ __align__(16) float g_ell_w[NN * ELLW];
__device__ __align__(16) float g_y1[NN * 512];
__device__ __align__(16) float g_t1[NN * 512];
__device__ __align__(16) float g_y2[NN * 256];
__device__ __align__(16) float g_p2[NN * 256];
__device__ __align__(16) float g_tx2[NN * 256];
__device__ __align__(16) float g_y3[NN * 128];
__device__ __align__(16) float g_sums[896];
__device__ __align__(16) float g_ssqs[896];
__device__ __align__(16) float g_bnsc[896];
__device__ __align__(16) float g_bnsh[896];

__device__ __forceinline__ float* buf(int id) {
    switch (id) {
        case 1: return g_y1;
        case 2: return g_t1;
        case 3: return g_y2;
        case 4: return g_p2;
        case 5: return g_tx2;
        case 6: return g_y3;
    }
    return nullptr;
}

// ---------------- graph build (ELL by dst) ----------------
__global__ void k_init_graph() {
    int i = blockIdx.x * blockDim.x + threadIdx.x;
    if (i < NN) { g_deg[i] = 0.0f; g_cnt[i] = 0; }
    if (i < 896) { g_sums[i] = 0.0f; g_ssqs[i] = 0.0f; }
}
__global__ void k_deg(const int* __restrict__ ei, const float* __restrict__ ea) {
    int e = blockIdx.x * blockDim.x + threadIdx.x;
    if (e >= EE) return;
    atomicAdd(&g_deg[ei[e]], ea[e]);
}
__global__ void k_norm_push(const int* __restrict__ ei, const float* __restrict__ ea) {
    int e = blockIdx.x * blockDim.x + threadIdx.x;
    if (e >= EE) return;
    int s = ei[e];
    int d = ei[EE + e];
    float ds = g_deg[s], dd = g_deg[d];
    float is = (ds > 0.0f) ? rsqrtf(ds) : 0.0f;
    float id = (dd > 0.0f) ? rsqrtf(dd) : 0.0f;
    float w = -is * ea[e] * id;
    int pos = atomicAdd(&g_cnt[d], 1);
    g_ell_src[d * ELLW + pos] = s;
    g_ell_w[d * ELLW + pos] = w;
}

// ---------------- BN coefficients ----------------
__global__ void k_bn_coef(const float* __restrict__ gamma, const float* __restrict__ beta,
                          int n, int F, int soff) {
    int f = threadIdx.x;
    if (f >= F) return;
    float inv_n = 1.0f / (float)n;
    float mu = g_sums[soff + f] * inv_n;
    float var = g_ssqs[soff + f] * inv_n - mu * mu;
    float sc = gamma[f] * rsqrtf(var + EPS);
    g_bnsc[soff + f] = sc;
    g_bnsh[soff + f] = beta[f] - mu * sc;
}

// ---------------- tf32 GEMM: BM=64, BN=128, BKT=16, fragment-major A+B (XOR-swizzled) ----------------
#define BMT 64
#define BNT 128
#define BKT 16
#define NF 4
#define A_STAGE (2 * NF * 128)   // 1024 floats
#define B_STAGE 2048             // 2 kh * 4 g * 2 reg * 128 floats

__device__ __forceinline__ unsigned f2tf(float x) {
    unsigned u;
    asm("cvt.rna.tf32.f32 %0, %1;" : "=r"(u) : "f"(x));
    return u;
}
__device__ __forceinline__ unsigned fui(float x) { return __float_as_uint(x); }

__global__ __launch_bounds__(256, 4) void gemm_tf32(
    const float* __restrict__ Aext, int aid0, int aid1, int aid2,
    const float* __restrict__ B0, const float* __restrict__ B1, const float* __restrict__ B2,
    const float* __restrict__ bias, int Cid,
    int M, int N, int Kseg, int segs, int soff,
    int coff0, int coff1, int coff2)
{
    __shared__ __align__(16) float As[2][A_STAGE];
    __shared__ __align__(16) float Bsf[2][B_STAGE];

    const float* Ap[3];
    Ap[0] = Aext ? Aext : buf(aid0);
    Ap[1] = buf(aid1);
    Ap[2] = buf(aid2);
    const float* Bp[3] = {B0, B1, B2};
    float* C = buf(Cid);

    const int tid = threadIdx.x;
    const int lane = tid & 31;
    const int warp = tid >> 5;
    const int qr = lane >> 2;
    const int qc = lane & 3;
    const int wm = (warp & 1) * 32;
    const int ms0 = (warp & 1) * 2;
    const int wn = (warp >> 1) * 32;

    const int row0 = blockIdx.y * BMT;
    const int col0 = blockIdx.x * BNT;

    // ---- A loader (validated in R8): one float4 per thread ----
    const int arow = tid >> 2;
    const int ak = (tid & 3) << 2;
    const bool avalid = (row0 + arow) < M;
    const int wr = arow & 15;
    const int wms = arow >> 4;
    const int wkh = ak >> 3;
    const int wkb = (ak >> 2) & 1;
    const int xsw = ((wr >> 1) & 3) << 2;
    const int awbase = (wkh * NF + wms) * 128 + ((wr & 7) << 4) + (wr >> 3) + (wkb << 1);

    // A fragment read base
    const int rpos = (qr << 2) + (qc ^ ((qr >> 1) & 3));
    const int ardbase = ms0 * 128 + (rpos << 2);

    // ---- B loader: rows brow(+8), cols bcol..bcol+3 -> XOR-swizzled fragment pages ----
    const int brow = tid >> 5;                  // 0..7 (+8 via it)
    const int bcol = (tid & 31) << 2;
    const int bg = bcol >> 5;                   // n-group 0..3
    const int bj = (bcol >> 3) & 3;             // j position within lane float4
    const int bqr0 = bcol & 7;                  // base qr (0 or 4)
    const int breg = brow >> 2;                 // b0/b1 page
    const int bqc = brow & 3;                   // qc
    // element e (n = bcol+e) -> lane l = 4*(bqr0+e)+bqc; stored slot = l ^ bg ^ ((l&16)>>2)
    int bwoff[4];
#pragma unroll
    for (int e = 0; e < 4; e++) {
        int l = 4 * (bqr0 + e) + bqc;
        int slot = l ^ bg ^ ((l & 16) >> 2);
        bwoff[e] = bg * 256 + breg * 128 + slot * 4 + bj;
    }

    // B fragment read: lane slot with matching XOR permutation
    const int bgr = warp >> 1;
    const int rslot = lane ^ bgr ^ ((lane & 16) >> 2);
    const int brdbase = bgr * 256 + rslot * 4;

    float acc[2][4][4];
#pragma unroll
    for (int i = 0; i < 2; i++)
#pragma unroll
        for (int j = 0; j < 4; j++)
#pragma unroll
            for (int e = 0; e < 4; e++) acc[i][j][e] = 0.0f;

    const int K = Kseg * segs;

    float4 rA, rB[2];
    auto fetch = [&](int k0) {
        const int seg = k0 / Kseg;
        const int kloc = k0 - seg * Kseg;
        const int coff = (seg == 0) ? coff0 : (seg == 1) ? coff1 : coff2;
        const float* A = Ap[seg];
        const float* B = Bp[seg];
        rA = make_float4(0.f, 0.f, 0.f, 0.f);
        if (avalid) rA = *(const float4*)(A + (size_t)(row0 + arow) * Kseg + kloc + ak);
        if (coff >= 0) {
            float4 sc = *(const float4*)(g_bnsc + coff + kloc + ak);
            float4 sh = *(const float4*)(g_bnsh + coff + kloc + ak);
            rA.x = fmaxf(fmaf(rA.x, sc.x, sh.x), 0.f);
            rA.y = fmaxf(fmaf(rA.y, sc.y, sh.y), 0.f);
            rA.z = fmaxf(fmaf(rA.z, sc.z, sh.z), 0.f);
            rA.w = fmaxf(fmaf(rA.w, sc.w, sh.w), 0.f);
        }
#pragma unroll
        for (int it = 0; it < 2; it++)
            rB[it] = *(const float4*)(B + (size_t)(kloc + brow + it * 8) * N + col0 + bcol);
    };
    auto commit = [&](int s) {
        float* Aw = As[s];
        Aw[awbase + ((0 << 2) ^ xsw)] = __uint_as_float(f2tf(rA.x));
        Aw[awbase + ((1 << 2) ^ xsw)] = __uint_as_float(f2tf(rA.y));
        Aw[awbase + ((2 << 2) ^ xsw)] = __uint_as_float(f2tf(rA.z));
        Aw[awbase + ((3 << 2) ^ xsw)] = __uint_as_float(f2tf(rA.w));
        float* Bw = Bsf[s];
#pragma unroll
        for (int it = 0; it < 2; it++) {
            float* p = Bw + it * 1024;
            p[bwoff[0]] = __uint_as_float(f2tf(rB[it].x));
            p[bwoff[1]] = __uint_as_float(f2tf(rB[it].y));
            p[bwoff[2]] = __uint_as_float(f2tf(rB[it].z));
            p[bwoff[3]] = __uint_as_float(f2tf(rB[it].w));
        }
    };

    fetch(0);
    commit(0);
    __syncthreads();

    int cur = 0;
    for (int k0 = 0; k0 < K; k0 += BKT, cur ^= 1) {
        const bool hasNext = (k0 + BKT) < K;
        if (hasNext) fetch(k0 + BKT);

        const float* Ac = As[cur];
        const float* Bc = Bsf[cur];
#pragma unroll
        for (int kh = 0; kh < 2; kh++) {
            const float* Af = Ac + kh * (NF * 128) + ardbase;
            float4 fa0 = *(const float4*)(Af);
            float4 fa1 = *(const float4*)(Af + 128);
            const float* Bf = Bc + kh * 1024 + brdbase;
            float4 qb0 = *(const float4*)(Bf);          // b0 regs, j=0..3
            float4 qb1 = *(const float4*)(Bf + 128);    // b1 regs, j=0..3
            const unsigned b0a[4] = {fui(qb0.x), fui(qb0.y), fui(qb0.z), fui(qb0.w)};
            const unsigned b1a[4] = {fui(qb1.x), fui(qb1.y), fui(qb1.z), fui(qb1.w)};
#pragma unroll
            for (int j = 0; j < 4; j++) {
                asm volatile(
                    "mma.sync.aligned.m16n8k8.row.col.f32.tf32.tf32.f32 "
                    "{%0,%1,%2,%3}, {%4,%5,%6,%7}, {%8,%9}, {%0,%1,%2,%3};"
                    : "+f"(acc[0][j][0]), "+f"(acc[0][j][1]),
                      "+f"(acc[0][j][2]), "+f"(acc[0][j][3])
                    : "r"(fui(fa0.x)), "r"(fui(fa0.y)), "r"(fui(fa0.z)), "r"(fui(fa0.w)),
                      "r"(b0a[j]), "r"(b1a[j]));
                asm volatile(
                    "mma.sync.aligned.m16n8k8.row.col.f32.tf32.tf32.f32 "
                    "{%0,%1,%2,%3}, {%4,%5,%6,%7}, {%8,%9}, {%0,%1,%2,%3};"
                    : "+f"(acc[1][j][0]), "+f"(acc[1][j][1]),
                      "+f"(acc[1][j][2]), "+f"(acc[1][j][3])
                    : "r"(fui(fa1.x)), "r"(fui(fa1.y)), "r"(fui(fa1.z)), "r"(fui(fa1.w)),
                      "r"(b0a[j]), "r"(b1a[j]));
            }
        }

        if (hasNext) commit(cur ^ 1);
        __syncthreads();
    }

    // ---- epilogue: bias add, store raw, fused BN stats ----
#pragma unroll
    for (int j = 0; j < 4; j++) {
        int c = col0 + wn + 8 * j + 2 * qc;
        float bx = bias[c], by = bias[c + 1];
#pragma unroll
        for (int i = 0; i < 2; i++) {
            acc[i][j][0] += bx; acc[i][j][1] += by;
            acc[i][j][2] += bx; acc[i][j][3] += by;
        }
    }
#pragma unroll
    for (int i = 0; i < 2; i++) {
        int r = row0 + wm + 16 * i + qr;
#pragma unroll
        for (int j = 0; j < 4; j++) {
            int c = col0 + wn + 8 * j + 2 * qc;
            if (r < M)
                *(float2*)(C + (size_t)r * N + c) = make_float2(acc[i][j][0], acc[i][j][1]);
            if (r + 8 < M)
                *(float2*)(C + (size_t)(r + 8) * N + c) = make_float2(acc[i][j][2], acc[i][j][3]);
        }
    }
#pragma unroll
    for (int j = 0; j < 4; j++) {
        float s0 = 0.f, q0 = 0.f, s1 = 0.f, q1 = 0.f;
#pragma unroll
        for (int i = 0; i < 2; i++) {
            int r = row0 + wm + 16 * i + qr;
            if (r < M) {
                s0 += acc[i][j][0]; q0 += acc[i][j][0] * acc[i][j][0];
                s1 += acc[i][j][1]; q1 += acc[i][j][1] * acc[i][j][1];
            }
            if (r + 8 < M) {
                s0 += acc[i][j][2]; q0 += acc[i][j][2] * acc[i][j][2];
                s1 += acc[i][j][3]; q1 += acc[i][j][3] * acc[i][j][3];
            }
        }
#pragma unroll
        for (int off = 4; off < 32; off <<= 1) {
            s0 += __shfl_xor_sync(0xffffffff, s0, off);
            q0 += __shfl_xor_sync(0xffffffff, q0, off);
            s1 += __shfl_xor_sync(0xffffffff, s1, off);
            q1 += __shfl_xor_sync(0xffffffff, q1, off);
        }
        if (qr == 0) {
            int c = col0 + wn + 8 * j + 2 * qc;
            atomicAdd(&g_sums[soff + c], s0);
            atomicAdd(&g_ssqs[soff + c], q0);
            atomicAdd(&g_sums[soff + c + 1], s1);
            atomicAdd(&g_ssqs[soff + c + 1], q1);
        }
    }
}

// ---------------- propagation (ELL by dst; BN+ReLU applied to gathered h) ----------------
__global__ void k_prop(int hid, int outid, int F, int coff) {
    const float* h = buf(hid);
    float* out = buf(outid);
    int node = blockIdx.x;
    int t = threadIdx.x;
    int cnt = g_cnt[node];
    int base = node * ELLW;
    float4 sc = make_float4(1.f, 1.f, 1.f, 1.f), sh = make_float4(0.f, 0.f, 0.f, 0.f);
    bool useC = coff >= 0;
    if (useC) {
        sc = *(const float4*)(g_bnsc + coff + t * 4);
        sh = *(const float4*)(g_bnsh + coff + t * 4);
    }
    float4 acc = make_float4(0.f, 0.f, 0.f, 0.f);
    for (int e = 0; e < cnt; e++) {
        int s = g_ell_src[base + e];
        float w = g_ell_w[base + e];
        float4 v = *(const float4*)(h + (size_t)s * F + t * 4);
        if (useC) {
            v.x = fmaxf(fmaf(v.x, sc.x, sh.x), 0.f);
            v.y = fmaxf(fmaf(v.y, sc.y, sh.y), 0.f);
            v.z = fmaxf(fmaf(v.z, sc.z, sh.z), 0.f);
            v.w = fmaxf(fmaf(v.w, sc.w, sh.w), 0.f);
        }
        acc.x += w * v.x; acc.y += w * v.y; acc.z += w * v.z; acc.w += w * v.w;
    }
    *(float4*)(out + (size_t)node * F + t * 4) = acc;
}

__global__ void k_prop_cheb(int hid, int subid, int outid, int F, int subcoff) {
    const float* h = buf(hid);
    const float* sub = buf(subid);
    float* out = buf(outid);
    int node = blockIdx.x;
    int t = threadIdx.x;
    int cnt = g_cnt[node];
    int base = node * ELLW;
    float4 acc = make_float4(0.f, 0.f, 0.f, 0.f);
    for (int e = 0; e < cnt; e++) {
        int s = g_ell_src[base + e];
        float w = g_ell_w[base + e];
        float4 v = *(const float4*)(h + (size_t)s * F + t * 4);
        acc.x += w * v.x; acc.y += w * v.y; acc.z += w * v.z; acc.w += w * v.w;
    }
    float4 sc = *(const float4*)(g_bnsc + subcoff + t * 4);
    float4 sh = *(const float4*)(g_bnsh + subcoff + t * 4);
    float4 sv = *(const float4*)(sub + (size_t)node * F + t * 4);
    sv.x = fmaxf(fmaf(sv.x, sc.x, sh.x), 0.f);
    sv.y = fmaxf(fmaf(sv.y, sc.y, sh.y), 0.f);
    sv.z = fmaxf(fmaf(sv.z, sc.z, sh.z), 0.f);
    sv.w = fmaxf(fmaf(sv.w, sc.w, sh.w), 0.f);
    float4 r;
    r.x = 2.0f * acc.x - sv.x;
    r.y = 2.0f * acc.y - sv.y;
    r.z = 2.0f * acc.z - sv.z;
    r.w = 2.0f * acc.w - sv.w;
    *(float4*)(out + (size_t)node * F + t * 4) = r;
}

// ---------------- fc (bn3 on load; 128 -> 6) + log_softmax ----------------
__global__ void k_fc(const float* __restrict__ W,
                     const float* __restrict__ bias, float* __restrict__ out, int n) {
    const float* h = g_y3;
    int gtid = blockIdx.x * blockDim.x + threadIdx.x;
    int node = gtid >> 5;
    int lane = gtid & 31;
    if (node >= n) return;
    float hv[4];
#pragma unroll
    for (int k = 0; k < 4; k++) {
        int col = lane + 32 * k;
        float raw = h[(size_t)node * 128 + col];
        hv[k] = fmaf(raw, g_bnsc[768 + col], g_bnsh[768 + col]);
    }
    float logit[6];
#pragma unroll
    for (int j = 0; j < 6; j++) {
        float s = 0.0f;
#pragma unroll
        for (int k = 0; k < 4; k++) s += hv[k] * W[(lane + 32 * k) * 6 + j];
#pragma unroll
        for (int o = 16; o > 0; o >>= 1) s += __shfl_xor_sync(0xffffffff, s, o);
        logit[j] = s + bias[j];
    }
    if (lane == 0) {
        float mx = logit[0];
#pragma unroll
        for (int j = 1; j < 6; j++) mx = fmaxf(mx, logit[j]);
        float se = 0.0f;
#pragma unroll
        for (int j = 0; j < 6; j++) se += expf(logit[j] - mx);
        float lse = mx + logf(se);
#pragma unroll
        for (int j = 0; j < 6; j++) out[(size_t)node * 6 + j] = logit[j] - lse;
    }
}

// ---------------- launch ----------------
extern "C" void kernel_launch(void* const* d_in, const int* in_sizes, int n_in,
                              void* d_out, int out_size) {
    const float* x    = (const float*)d_in[0];
    const int*   ei   = (const int*)d_in[1];
    const float* ea   = (const float*)d_in[2];
    const float* W1_0 = (const float*)d_in[3];
    const float* b1   = (const float*)d_in[4];
    const float* g1   = (const float*)d_in[5];
    const float* be1  = (const float*)d_in[6];
    const float* W2_0 = (const float*)d_in[7];
    const float* W2_1 = (const float*)d_in[8];
    const float* b2   = (const float*)d_in[9];
    const float* g2   = (const float*)d_in[10];
    const float* be2  = (const float*)d_in[11];
    const float* W3_0 = (const float*)d_in[12];
    const float* W3_1 = (const float*)d_in[13];
    const float* W3_2 = (const float*)d_in[14];
    const float* b3   = (const float*)d_in[15];
    const float* g3   = (const float*)d_in[16];
    const float* be3  = (const float*)d_in[17];
    const float* fcW  = (const float*)d_in[18];
    const float* fcb  = (const float*)d_in[19];
    float* out = (float*)d_out;

    // ---- graph normalization + ELL build ----
    k_init_graph<<<CEILDIV(NN, 256), 256>>>();
    k_deg<<<CEILDIV(EE, 256), 256>>>(ei, ea);
    k_norm_push<<<CEILDIV(EE, 256), 256>>>(ei, ea);

    const int GY = CEILDIV(NN, BMT);   // 157

    // ---- layer 1 ----
    gemm_tf32<<<dim3(512 / BNT, GY), 256>>>(
        x, 0, 0, 0, W1_0, nullptr, nullptr, b1, 1, NN, 512, 768, 1, 0, -1, -1, -1);
    k_bn_coef<<<1, 512>>>(g1, be1, NN, 512, 0);

    // ---- layer 2 ----
    k_prop<<<NN, 128>>>(1, 2, 512, 0);
    gemm_tf32<<<dim3(256 / BNT, GY), 256>>>(
        nullptr, 1, 2, 0, W2_0, W2_1, nullptr, b2, 3, NN, 256, 512, 2, 512, 0, -1, -1);
    k_bn_coef<<<1, 256>>>(g2, be2, NN, 256, 512);

    // ---- layer 3 ----
    k_prop<<<NN, 64>>>(3, 4, 256, 512);
    k_prop_cheb<<<NN, 64>>>(4, 3, 5, 256, 512);
    gemm_tf32<<<dim3(128 / BNT, GY), 256>>>(
        nullptr, 3, 4, 5, W3_0, W3_1, W3_2, b3, 6, NN, 128, 256, 3, 768, 512, -1, -1);
    k_bn_coef<<<1, 128>>>(g3, be3, NN, 128, 768);

    // ---- fc (bn3 fused) + log_softmax ----
    k_fc<<<CEILDIV(NN * 32, 256), 256>>>(fcW, fcb, out, NN);
}

// round 11
// speedup vs baseline: 1.1991x; 1.0661x over previous
#include <cuda_runtime.h>

#define NN 10000
#define EE 160000
#define EPS 1e-5f
#define ELLW 64
#define CEILDIV(a,b) (((a)+(b)-1)/(b))

// ---------------- scratch (static device globals; no allocation) ----------------
__device__ __align__(16) float g_deg[NN];
__device__ __align__(16) int   g_cnt[NN];
__device__ __align__(16) int   g_ell_src[NN * ELLW];
__device__ __align__(16) float g_ell_w[NN * ELLW];
__device__ __align__(16) float g_y1[NN * 512];
__device__ __align__(16) float g_t1[NN * 512];
__device__ __align__(16) float g_y2[NN * 256];
__device__ __align__(16) float g_p2[NN * 256];
__device__ __align__(16) float g_tx2[NN * 256];
__device__ __align__(16) float g_y3[NN * 128];
__device__ __align__(16) float g_pB1[768 * 512];   // pre-packed tf32 B fragments
__device__ __align__(16) float g_pB2[1024 * 256];
__device__ __align__(16) float g_pB3[768 * 128];
__device__ __align__(16) float g_sums[896];
__device__ __align__(16) float g_ssqs[896];
__device__ __align__(16) float g_bnsc[896];
__device__ __align__(16) float g_bnsh[896];

__device__ __forceinline__ float* buf(int id) {
    switch (id) {
        case 1: return g_y1;
        case 2: return g_t1;
        case 3: return g_y2;
        case 4: return g_p2;
        case 5: return g_tx2;
        case 6: return g_y3;
        case 7: return g_pB1;
        case 8: return g_pB2;
        case 9: return g_pB3;
    }
    return nullptr;
}

__device__ __forceinline__ unsigned f2tf(float x) {
    unsigned u;
    asm("cvt.rna.tf32.f32 %0, %1;" : "=r"(u) : "f"(x));
    return u;
}
__device__ __forceinline__ unsigned fui(float x) { return __float_as_uint(x); }

// ---------------- graph build (ELL by dst) ----------------
__global__ void k_init_graph() {
    int i = blockIdx.x * blockDim.x + threadIdx.x;
    if (i < NN) { g_deg[i] = 0.0f; g_cnt[i] = 0; }
    if (i < 896) { g_sums[i] = 0.0f; g_ssqs[i] = 0.0f; }
}
__global__ void k_deg(const int* __restrict__ ei, const float* __restrict__ ea) {
    int e = blockIdx.x * blockDim.x + threadIdx.x;
    if (e >= EE) return;
    atomicAdd(&g_deg[ei[e]], ea[e]);
}
__global__ void k_norm_push(const int* __restrict__ ei, const float* __restrict__ ea) {
    int e = blockIdx.x * blockDim.x + threadIdx.x;
    if (e >= EE) return;
    int s = ei[e];
    int d = ei[EE + e];
    float ds = g_deg[s], dd = g_deg[d];
    float is = (ds > 0.0f) ? rsqrtf(ds) : 0.0f;
    float id = (dd > 0.0f) ? rsqrtf(dd) : 0.0f;
    float w = -is * ea[e] * id;
    int pos = atomicAdd(&g_cnt[d], 1);
    g_ell_src[d * ELLW + pos] = s;
    g_ell_w[d * ELLW + pos] = w;
}

// ---------------- BN coefficients ----------------
__global__ void k_bn_coef(const float* __restrict__ gamma, const float* __restrict__ beta,
                          int n, int F, int soff) {
    int f = threadIdx.x;
    if (f >= F) return;
    float inv_n = 1.0f / (float)n;
    float mu = g_sums[soff + f] * inv_n;
    float var = g_ssqs[soff + f] * inv_n - mu * mu;
    float sc = gamma[f] * rsqrtf(var + EPS);
    g_bnsc[soff + f] = sc;
    g_bnsh[soff + f] = beta[f] - mu * sc;
}

// ---------------- B pre-pack: mma-fragment-major, tf32-preconverted ----------------
// pack[(kb*ng + gg)*256 + l*8 + j*2 + reg] = tf32(B[kb*8 + qc + 4*reg][gg*32 + 8*j + qr])
__global__ void k_packB(const float* __restrict__ B0, const float* __restrict__ B1,
                        const float* __restrict__ B2, int Kseg, int N, int K, int dstid) {
    int idx = blockIdx.x * blockDim.x + threadIdx.x;
    if (idx >= K * N) return;
    float* dst = buf(dstid);
    int low = idx & 7;
    int j = low >> 1, reg = low & 1;
    int l = (idx >> 3) & 31;
    int rest = idx >> 8;
    int ng = N >> 5;
    int gg = rest % ng;
    int kb = rest / ng;
    int qr = l >> 2, qc = l & 3;
    int row = kb * 8 + qc + 4 * reg;
    int col = gg * 32 + 8 * j + qr;
    int seg = row / Kseg;
    int rloc = row - seg * Kseg;
    const float* B = (seg == 0) ? B0 : (seg == 1) ? B1 : B2;
    dst[idx] = __uint_as_float(f2tf(B[rloc * N + col]));
}

// ---------------- tf32 GEMM: BM=64, BN=128, BKT=16; A fragment-major smem (R8-validated),
// B fragments register-direct from pre-packed GMEM ----------------
#define BMT 64
#define BNT 128
#define BKT 16
#define NF 4
#define A_STAGE (2 * NF * 128)   // 1024 floats

__global__ __launch_bounds__(256, 2) void gemm_tf32(
    const float* __restrict__ Aext, int aid0, int aid1, int aid2, int pBid,
    const float* __restrict__ bias, int Cid,
    int M, int N, int Kseg, int segs, int soff, int coff0)
{
    __shared__ __align__(16) float As[2][A_STAGE];

    const float* Ap[3];
    Ap[0] = Aext ? Aext : buf(aid0);
    Ap[1] = buf(aid1);
    Ap[2] = buf(aid2);
    float* C = buf(Cid);

    const int tid = threadIdx.x;
    const int lane = tid & 31;
    const int warp = tid >> 5;
    const int qr = lane >> 2;
    const int qc = lane & 3;
    const int wm = (warp & 1) * 32;
    const int ms0 = (warp & 1) * 2;
    const int wn = (warp >> 1) * 32;

    const int row0 = blockIdx.y * BMT;
    const int col0 = blockIdx.x * BNT;

    // ---- A loader (validated in R8): one float4 per thread into fragment-major smem ----
    const int arow = tid >> 2;
    const int ak = (tid & 3) << 2;
    const bool avalid = (row0 + arow) < M;
    const int wr = arow & 15;
    const int wms = arow >> 4;
    const int wkh = ak >> 3;
    const int wkb = (ak >> 2) & 1;
    const int xsw = ((wr >> 1) & 3) << 2;
    const int awbase = (wkh * NF + wms) * 128 + ((wr & 7) << 4) + (wr >> 3) + (wkb << 1);

    // A fragment read base
    const int rpos = (qr << 2) + (qc ^ ((qr >> 1) & 3));
    const int ardbase = ms0 * 128 + (rpos << 2);

    // ---- B: register-direct from pre-packed GMEM ----
    const int khoff = (N >> 5) * 256;      // floats per kb block
    const int bstep = 2 * khoff;           // per BKT=16 iteration
    const float* pB = buf(pBid) + ((col0 >> 5) + (warp >> 1)) * 256 + lane * 8;

    float acc[2][4][4];
#pragma unroll
    for (int i = 0; i < 2; i++)
#pragma unroll
        for (int j = 0; j < 4; j++)
#pragma unroll
            for (int e = 0; e < 4; e++) acc[i][j][e] = 0.0f;

    const size_t aoff = (size_t)(row0 + arow) * Kseg + ak;
    const float* pA = Ap[0] + aoff;
    const float* psc = g_bnsc + (coff0 >= 0 ? coff0 : 0) + ak;
    const float* psh = g_bnsh + (coff0 >= 0 ? coff0 : 0) + ak;
    int segi = 0, kcnt = 0;
    const int kperseg = Kseg / BKT;
    const int niter = kperseg * segs;

    float4 rA;
    float4 rBc[4], rBn[4];

    auto fetchA = [&]() {
        rA = make_float4(0.f, 0.f, 0.f, 0.f);
        if (avalid) rA = *(const float4*)pA;
        if (coff0 >= 0 && segi == 0) {
            float4 sc = *(const float4*)psc;
            float4 sh = *(const float4*)psh;
            rA.x = fmaxf(fmaf(rA.x, sc.x, sh.x), 0.f);
            rA.y = fmaxf(fmaf(rA.y, sc.y, sh.y), 0.f);
            rA.z = fmaxf(fmaf(rA.z, sc.z, sh.z), 0.f);
            rA.w = fmaxf(fmaf(rA.w, sc.w, sh.w), 0.f);
        }
    };
    auto fetchB = [&](float4* r) {
        r[0] = *(const float4*)(pB);
        r[1] = *(const float4*)(pB + 4);
        r[2] = *(const float4*)(pB + khoff);
        r[3] = *(const float4*)(pB + khoff + 4);
    };
    auto advance = [&]() {
        kcnt++;
        if (kcnt == kperseg) {
            kcnt = 0; segi++;
            if (segi < segs) pA = ((segi == 1) ? Ap[1] : Ap[2]) + aoff;
        } else {
            pA += BKT;
        }
        psc += BKT; psh += BKT;
        pB += bstep;
    };
    auto commitA = [&](int s) {
        float* Aw = As[s];
        Aw[awbase + ((0 << 2) ^ xsw)] = __uint_as_float(f2tf(rA.x));
        Aw[awbase + ((1 << 2) ^ xsw)] = __uint_as_float(f2tf(rA.y));
        Aw[awbase + ((2 << 2) ^ xsw)] = __uint_as_float(f2tf(rA.z));
        Aw[awbase + ((3 << 2) ^ xsw)] = __uint_as_float(f2tf(rA.w));
    };

    fetchA();
    fetchB(rBc);
    advance();
    commitA(0);
    __syncthreads();

    int cur = 0;
    for (int it = 0; it < niter; it++, cur ^= 1) {
        const bool hasNext = (it + 1) < niter;
        if (hasNext) { fetchA(); fetchB(rBn); advance(); }

        const float* Ac = As[cur];
#pragma unroll
        for (int kh = 0; kh < 2; kh++) {
            const float* Af = Ac + kh * (NF * 128) + ardbase;
            float4 fa0 = *(const float4*)(Af);
            float4 fa1 = *(const float4*)(Af + 128);
            float4 q0 = rBc[kh * 2 + 0];
            float4 q1 = rBc[kh * 2 + 1];
            const unsigned b0a[4] = {fui(q0.x), fui(q0.z), fui(q1.x), fui(q1.z)};
            const unsigned b1a[4] = {fui(q0.y), fui(q0.w), fui(q1.y), fui(q1.w)};
#pragma unroll
            for (int j = 0; j < 4; j++) {
                asm volatile(
                    "mma.sync.aligned.m16n8k8.row.col.f32.tf32.tf32.f32 "
                    "{%0,%1,%2,%3}, {%4,%5,%6,%7}, {%8,%9}, {%0,%1,%2,%3};"
                    : "+f"(acc[0][j][0]), "+f"(acc[0][j][1]),
                      "+f"(acc[0][j][2]), "+f"(acc[0][j][3])
                    : "r"(fui(fa0.x)), "r"(fui(fa0.y)), "r"(fui(fa0.z)), "r"(fui(fa0.w)),
                      "r"(b0a[j]), "r"(b1a[j]));
                asm volatile(
                    "mma.sync.aligned.m16n8k8.row.col.f32.tf32.tf32.f32 "
                    "{%0,%1,%2,%3}, {%4,%5,%6,%7}, {%8,%9}, {%0,%1,%2,%3};"
                    : "+f"(acc[1][j][0]), "+f"(acc[1][j][1]),
                      "+f"(acc[1][j][2]), "+f"(acc[1][j][3])
                    : "r"(fui(fa1.x)), "r"(fui(fa1.y)), "r"(fui(fa1.z)), "r"(fui(fa1.w)),
                      "r"(b0a[j]), "r"(b1a[j]));
            }
        }

        if (hasNext) {
            commitA(cur ^ 1);
            rBc[0] = rBn[0]; rBc[1] = rBn[1]; rBc[2] = rBn[2]; rBc[3] = rBn[3];
        }
        __syncthreads();
    }

    // ---- epilogue: bias add, store raw, fused BN stats ----
#pragma unroll
    for (int j = 0; j < 4; j++) {
        int c = col0 + wn + 8 * j + 2 * qc;
        float bx = bias[c], by = bias[c + 1];
#pragma unroll
        for (int i = 0; i < 2; i++) {
            acc[i][j][0] += bx; acc[i][j][1] += by;
            acc[i][j][2] += bx; acc[i][j][3] += by;
        }
    }
#pragma unroll
    for (int i = 0; i < 2; i++) {
        int r = row0 + wm + 16 * i + qr;
#pragma unroll
        for (int j = 0; j < 4; j++) {
            int c = col0 + wn + 8 * j + 2 * qc;
            if (r < M)
                *(float2*)(C + (size_t)r * N + c) = make_float2(acc[i][j][0], acc[i][j][1]);
            if (r + 8 < M)
                *(float2*)(C + (size_t)(r + 8) * N + c) = make_float2(acc[i][j][2], acc[i][j][3]);
        }
    }
#pragma unroll
    for (int j = 0; j < 4; j++) {
        float s0 = 0.f, q0 = 0.f, s1 = 0.f, q1 = 0.f;
#pragma unroll
        for (int i = 0; i < 2; i++) {
            int r = row0 + wm + 16 * i + qr;
            if (r < M) {
                s0 += acc[i][j][0]; q0 += acc[i][j][0] * acc[i][j][0];
                s1 += acc[i][j][1]; q1 += acc[i][j][1] * acc[i][j][1];
            }
            if (r + 8 < M) {
                s0 += acc[i][j][2]; q0 += acc[i][j][2] * acc[i][j][2];
                s1 += acc[i][j][3]; q1 += acc[i][j][3] * acc[i][j][3];
            }
        }
#pragma unroll
        for (int off = 4; off < 32; off <<= 1) {
            s0 += __shfl_xor_sync(0xffffffff, s0, off);
            q0 += __shfl_xor_sync(0xffffffff, q0, off);
            s1 += __shfl_xor_sync(0xffffffff, s1, off);
            q1 += __shfl_xor_sync(0xffffffff, q1, off);
        }
        if (qr == 0) {
            int c = col0 + wn + 8 * j + 2 * qc;
            atomicAdd(&g_sums[soff + c], s0);
            atomicAdd(&g_ssqs[soff + c], q0);
            atomicAdd(&g_sums[soff + c + 1], s1);
            atomicAdd(&g_ssqs[soff + c + 1], q1);
        }
    }
}

// ---------------- propagation (ELL by dst; BN+ReLU applied to gathered h) ----------------
__global__ void k_prop(int hid, int outid, int F, int coff) {
    const float* h = buf(hid);
    float* out = buf(outid);
    int node = blockIdx.x;
    int t = threadIdx.x;
    int cnt = g_cnt[node];
    int base = node * ELLW;
    float4 sc = make_float4(1.f, 1.f, 1.f, 1.f), sh = make_float4(0.f, 0.f, 0.f, 0.f);
    bool useC = coff >= 0;
    if (useC) {
        sc = *(const float4*)(g_bnsc + coff + t * 4);
        sh = *(const float4*)(g_bnsh + coff + t * 4);
    }
    float4 acc = make_float4(0.f, 0.f, 0.f, 0.f);
    for (int e = 0; e < cnt; e++) {
        int s = g_ell_src[base + e];
        float w = g_ell_w[base + e];
        float4 v = *(const float4*)(h + (size_t)s * F + t * 4);
        if (useC) {
            v.x = fmaxf(fmaf(v.x, sc.x, sh.x), 0.f);
            v.y = fmaxf(fmaf(v.y, sc.y, sh.y), 0.f);
            v.z = fmaxf(fmaf(v.z, sc.z, sh.z), 0.f);
            v.w = fmaxf(fmaf(v.w, sc.w, sh.w), 0.f);
        }
        acc.x += w * v.x; acc.y += w * v.y; acc.z += w * v.z; acc.w += w * v.w;
    }
    *(float4*)(out + (size_t)node * F + t * 4) = acc;
}

__global__ void k_prop_cheb(int hid, int subid, int outid, int F, int subcoff) {
    const float* h = buf(hid);
    const float* sub = buf(subid);
    float* out = buf(outid);
    int node = blockIdx.x;
    int t = threadIdx.x;
    int cnt = g_cnt[node];
    int base = node * ELLW;
    float4 acc = make_float4(0.f, 0.f, 0.f, 0.f);
    for (int e = 0; e < cnt; e++) {
        int s = g_ell_src[base + e];
        float w = g_ell_w[base + e];
        float4 v = *(const float4*)(h + (size_t)s * F + t * 4);
        acc.x += w * v.x; acc.y += w * v.y; acc.z += w * v.z; acc.w += w * v.w;
    }
    float4 sc = *(const float4*)(g_bnsc + subcoff + t * 4);
    float4 sh = *(const float4*)(g_bnsh + subcoff + t * 4);
    float4 sv = *(const float4*)(sub + (size_t)node * F + t * 4);
    sv.x = fmaxf(fmaf(sv.x, sc.x, sh.x), 0.f);
    sv.y = fmaxf(fmaf(sv.y, sc.y, sh.y), 0.f);
    sv.z = fmaxf(fmaf(sv.z, sc.z, sh.z), 0.f);
    sv.w = fmaxf(fmaf(sv.w, sc.w, sh.w), 0.f);
    float4 r;
    r.x = 2.0f * acc.x - sv.x;
    r.y = 2.0f * acc.y - sv.y;
    r.z = 2.0f * acc.z - sv.z;
    r.w = 2.0f * acc.w - sv.w;
    *(float4*)(out + (size_t)node * F + t * 4) = r;
}

// ---------------- fc (bn3 on load; 128 -> 6) + log_softmax ----------------
__global__ void k_fc(const float* __restrict__ W,
                     const float* __restrict__ bias, float* __restrict__ out, int n) {
    const float* h = g_y3;
    int gtid = blockIdx.x * blockDim.x + threadIdx.x;
    int node = gtid >> 5;
    int lane = gtid & 31;
    if (node >= n) return;
    float hv[4];
#pragma unroll
    for (int k = 0; k < 4; k++) {
        int col = lane + 32 * k;
        float raw = h[(size_t)node * 128 + col];
        hv[k] = fmaf(raw, g_bnsc[768 + col], g_bnsh[768 + col]);
    }
    float logit[6];
#pragma unroll
    for (int j = 0; j < 6; j++) {
        float s = 0.0f;
#pragma unroll
        for (int k = 0; k < 4; k++) s += hv[k] * W[(lane + 32 * k) * 6 + j];
#pragma unroll
        for (int o = 16; o > 0; o >>= 1) s += __shfl_xor_sync(0xffffffff, s, o);
        logit[j] = s + bias[j];
    }
    if (lane == 0) {
        float mx = logit[0];
#pragma unroll
        for (int j = 1; j < 6; j++) mx = fmaxf(mx, logit[j]);
        float se = 0.0f;
#pragma unroll
        for (int j = 0; j < 6; j++) se += expf(logit[j] - mx);
        float lse = mx + logf(se);
#pragma unroll
        for (int j = 0; j < 6; j++) out[(size_t)node * 6 + j] = logit[j] - lse;
    }
}

// ---------------- launch ----------------
extern "C" void kernel_launch(void* const* d_in, const int* in_sizes, int n_in,
                              void* d_out, int out_size) {
    const float* x    = (const float*)d_in[0];
    const int*   ei   = (const int*)d_in[1];
    const float* ea   = (const float*)d_in[2];
    const float* W1_0 = (const float*)d_in[3];
    const float* b1   = (const float*)d_in[4];
    const float* g1   = (const float*)d_in[5];
    const float* be1  = (const float*)d_in[6];
    const float* W2_0 = (const float*)d_in[7];
    const float* W2_1 = (const float*)d_in[8];
    const float* b2   = (const float*)d_in[9];
    const float* g2   = (const float*)d_in[10];
    const float* be2  = (const float*)d_in[11];
    const float* W3_0 = (const float*)d_in[12];
    const float* W3_1 = (const float*)d_in[13];
    const float* W3_2 = (const float*)d_in[14];
    const float* b3   = (const float*)d_in[15];
    const float* g3   = (const float*)d_in[16];
    const float* be3  = (const float*)d_in[17];
    const float* fcW  = (const float*)d_in[18];
    const float* fcb  = (const float*)d_in[19];
    float* out = (float*)d_out;

    // ---- one-time B fragment pre-pack (weights only) ----
    k_packB<<<CEILDIV(768 * 512, 256), 256>>>(W1_0, nullptr, nullptr, 768, 512, 768, 7);
    k_packB<<<CEILDIV(1024 * 256, 256), 256>>>(W2_0, W2_1, nullptr, 512, 256, 1024, 8);
    k_packB<<<CEILDIV(768 * 128, 256), 256>>>(W3_0, W3_1, W3_2, 256, 128, 768, 9);

    // ---- graph normalization + ELL build ----
    k_init_graph<<<CEILDIV(NN, 256), 256>>>();
    k_deg<<<CEILDIV(EE, 256), 256>>>(ei, ea);
    k_norm_push<<<CEILDIV(EE, 256), 256>>>(ei, ea);

    const int GY = CEILDIV(NN, BMT);   // 157

    // ---- layer 1 ----
    gemm_tf32<<<dim3(512 / BNT, GY), 256>>>(
        x, 0, 0, 0, 7, b1, 1, NN, 512, 768, 1, 0, -1);
    k_bn_coef<<<1, 512>>>(g1, be1, NN, 512, 0);

    // ---- layer 2 ----
    k_prop<<<NN, 128>>>(1, 2, 512, 0);
    gemm_tf32<<<dim3(256 / BNT, GY), 256>>>(
        nullptr, 1, 2, 0, 8, b2, 3, NN, 256, 512, 2, 512, 0);
    k_bn_coef<<<1, 256>>>(g2, be2, NN, 256, 512);

    // ---- layer 3 ----
    k_prop<<<NN, 64>>>(3, 4, 256, 512);
    k_prop_cheb<<<NN, 64>>>(4, 3, 5, 256, 512);
    gemm_tf32<<<dim3(128 / BNT, GY), 256>>>(
        nullptr, 3, 4, 5, 9, b3, 6, NN, 128, 256, 3, 768, 512);
    k_bn_coef<<<1, 128>>>(g3, be3, NN, 128, 768);

    // ---- fc (bn3 fused) + log_softmax ----
    k_fc<<<CEILDIV(NN * 32, 256), 256>>>(fcW, fcb, out, NN);
}

// round 12
// speedup vs baseline: 1.3678x; 1.1407x over previous
#include <cuda_runtime.h>

#define NN 10000
#define EE 160000
#define EPS 1e-5f
#define ELLW 64
#define CEILDIV(a,b) (((a)+(b)-1)/(b))

// ---------------- scratch (static device globals; no allocation) ----------------
__device__ __align__(16) float g_deg[NN];
__device__ __align__(16) int   g_cnt[NN];
__device__ __align__(16) int   g_ell_src[NN * ELLW];
__device__ __align__(16) float g_ell_w[NN * ELLW];
__device__ __align__(16) float g_y1[NN * 512];
__device__ __align__(16) float g_t1[NN * 512];
__device__ __align__(16) float g_y2[NN * 256];
__device__ __align__(16) float g_p2[NN * 256];
__device__ __align__(16) float g_tx2[NN * 256];
__device__ __align__(16) float g_y3[NN * 128];
__device__ __align__(16) float g_sums[896];
__device__ __align__(16) float g_ssqs[896];
__device__ __align__(16) float g_bnsc[896];
__device__ __align__(16) float g_bnsh[896];

__device__ __forceinline__ float* buf(int id) {
    switch (id) {
        case 1: return g_y1;
        case 2: return g_t1;
        case 3: return g_y2;
        case 4: return g_p2;
        case 5: return g_tx2;
        case 6: return g_y3;
    }
    return nullptr;
}

// ---------------- graph build (ELL by dst) ----------------
__global__ void k_init_graph() {
    int i = blockIdx.x * blockDim.x + threadIdx.x;
    if (i < NN) { g_deg[i] = 0.0f; g_cnt[i] = 0; }
    if (i < 896) { g_sums[i] = 0.0f; g_ssqs[i] = 0.0f; }
}
__global__ void k_deg(const int* __restrict__ ei, const float* __restrict__ ea) {
    int e = blockIdx.x * blockDim.x + threadIdx.x;
    if (e >= EE) return;
    atomicAdd(&g_deg[ei[e]], ea[e]);
}
__global__ void k_norm_push(const int* __restrict__ ei, const float* __restrict__ ea) {
    int e = blockIdx.x * blockDim.x + threadIdx.x;
    if (e >= EE) return;
    int s = ei[e];
    int d = ei[EE + e];
    float ds = g_deg[s], dd = g_deg[d];
    float is = (ds > 0.0f) ? rsqrtf(ds) : 0.0f;
    float id = (dd > 0.0f) ? rsqrtf(dd) : 0.0f;
    float w = -is * ea[e] * id;
    int pos = atomicAdd(&g_cnt[d], 1);
    g_ell_src[d * ELLW + pos] = s;
    g_ell_w[d * ELLW + pos] = w;
}

// ---------------- BN coefficients ----------------
__global__ void k_bn_coef(const float* __restrict__ gamma, const float* __restrict__ beta,
                          int n, int F, int soff) {
    int f = threadIdx.x;
    if (f >= F) return;
    float inv_n = 1.0f / (float)n;
    float mu = g_sums[soff + f] * inv_n;
    float var = g_ssqs[soff + f] * inv_n - mu * mu;
    float sc = gamma[f] * rsqrtf(var + EPS);
    g_bnsc[soff + f] = sc;
    g_bnsh[soff + f] = beta[f] - mu * sc;
}

// ---------------- tf32 GEMM (R8-exact): BM=64, BN=128, BKT=16, fragment-major A smem ----------------
#define BMT 64
#define BNT 128
#define BKT 16
#define NF 4
#define A_STAGE (2 * NF * 128)   // 1024 floats
#define BPAD 136

__device__ __forceinline__ unsigned f2tf(float x) {
    unsigned u;
    asm("cvt.rna.tf32.f32 %0, %1;" : "=r"(u) : "f"(x));
    return u;
}
__device__ __forceinline__ unsigned fui(float x) { return __float_as_uint(x); }

__global__ __launch_bounds__(256, 3) void gemm_tf32(
    const float* __restrict__ Aext, int aid0, int aid1, int aid2,
    const float* __restrict__ B0, const float* __restrict__ B1, const float* __restrict__ B2,
    const float* __restrict__ bias, int Cid,
    int M, int N, int Kseg, int segs, int soff,
    int coff0, int coff1, int coff2)
{
    __shared__ __align__(16) float As[2][A_STAGE];
    __shared__ __align__(16) float Bs[2][BKT][BPAD];

    const float* Ap[3];
    Ap[0] = Aext ? Aext : buf(aid0);
    Ap[1] = buf(aid1);
    Ap[2] = buf(aid2);
    const float* Bp[3] = {B0, B1, B2};
    float* C = buf(Cid);

    const int tid = threadIdx.x;
    const int lane = tid & 31;
    const int warp = tid >> 5;
    const int qr = lane >> 2;
    const int qc = lane & 3;
    const int wm = (warp & 1) * 32;
    const int ms0 = (warp & 1) * 2;
    const int wn = (warp >> 1) * 32;

    const int row0 = blockIdx.y * BMT;
    const int col0 = blockIdx.x * BNT;

    // A loader: one float4 per thread: row=tid/4, k=(tid&3)*4
    const int arow = tid >> 2;
    const int ak = (tid & 3) << 2;
    const bool avalid = (row0 + arow) < M;
    const int wr = arow & 15;
    const int wms = arow >> 4;
    const int wkh = ak >> 3;
    const int wkb = (ak >> 2) & 1;
    const int xsw = ((wr >> 1) & 3) << 2;
    const int awbase = (wkh * NF + wms) * 128 + ((wr & 7) << 4) + (wr >> 3) + (wkb << 1);

    // A fragment read base
    const int rpos = (qr << 2) + (qc ^ ((qr >> 1) & 3));
    const int ardbase = ms0 * 128 + (rpos << 2);

    // B loader
    const int brow = tid >> 5;
    const int bcol = (tid & 31) << 2;

    float acc[2][4][4];
#pragma unroll
    for (int i = 0; i < 2; i++)
#pragma unroll
        for (int j = 0; j < 4; j++)
#pragma unroll
            for (int e = 0; e < 4; e++) acc[i][j][e] = 0.0f;

    const int K = Kseg * segs;

    float4 rA, rB[2];
    auto fetch = [&](int k0) {
        const int seg = k0 / Kseg;
        const int kloc = k0 - seg * Kseg;
        const int coff = (seg == 0) ? coff0 : (seg == 1) ? coff1 : coff2;
        const float* A = Ap[seg];
        const float* B = Bp[seg];
        rA = make_float4(0.f, 0.f, 0.f, 0.f);
        if (avalid) rA = *(const float4*)(A + (size_t)(row0 + arow) * Kseg + kloc + ak);
        if (coff >= 0) {
            float4 sc = *(const float4*)(g_bnsc + coff + kloc + ak);
            float4 sh = *(const float4*)(g_bnsh + coff + kloc + ak);
            rA.x = fmaxf(fmaf(rA.x, sc.x, sh.x), 0.f);
            rA.y = fmaxf(fmaf(rA.y, sc.y, sh.y), 0.f);
            rA.z = fmaxf(fmaf(rA.z, sc.z, sh.z), 0.f);
            rA.w = fmaxf(fmaf(rA.w, sc.w, sh.w), 0.f);
        }
#pragma unroll
        for (int it = 0; it < 2; it++)
            rB[it] = *(const float4*)(B + (size_t)(kloc + brow + it * 8) * N + col0 + bcol);
    };
    auto commit = [&](int s) {
        float* Aw = As[s];
        Aw[awbase + ((0 << 2) ^ xsw)] = __uint_as_float(f2tf(rA.x));
        Aw[awbase + ((1 << 2) ^ xsw)] = __uint_as_float(f2tf(rA.y));
        Aw[awbase + ((2 << 2) ^ xsw)] = __uint_as_float(f2tf(rA.z));
        Aw[awbase + ((3 << 2) ^ xsw)] = __uint_as_float(f2tf(rA.w));
#pragma unroll
        for (int it = 0; it < 2; it++) {
            float4 w;
            w.x = __uint_as_float(f2tf(rB[it].x));
            w.y = __uint_as_float(f2tf(rB[it].y));
            w.z = __uint_as_float(f2tf(rB[it].z));
            w.w = __uint_as_float(f2tf(rB[it].w));
            *(float4*)&Bs[s][brow + it * 8][bcol] = w;
        }
    };

    fetch(0);
    commit(0);
    __syncthreads();

    int cur = 0;
    for (int k0 = 0; k0 < K; k0 += BKT, cur ^= 1) {
        const bool hasNext = (k0 + BKT) < K;
        if (hasNext) fetch(k0 + BKT);

        const float* Ac = As[cur];
        const float* Bc = &Bs[cur][0][0];
#pragma unroll
        for (int kh = 0; kh < 2; kh++) {
            const float* Af = Ac + kh * (NF * 128) + ardbase;
            float4 fa0 = *(const float4*)(Af);
            float4 fa1 = *(const float4*)(Af + 128);
            const float* Bk0 = Bc + (kh * 8 + qc) * BPAD + wn + qr;
            const float* Bk1 = Bk0 + 4 * BPAD;
#pragma unroll
            for (int j = 0; j < 4; j++) {
                unsigned b0 = fui(Bk0[8 * j]);
                unsigned b1 = fui(Bk1[8 * j]);
                asm volatile(
                    "mma.sync.aligned.m16n8k8.row.col.f32.tf32.tf32.f32 "
                    "{%0,%1,%2,%3}, {%4,%5,%6,%7}, {%8,%9}, {%0,%1,%2,%3};"
                    : "+f"(acc[0][j][0]), "+f"(acc[0][j][1]),
                      "+f"(acc[0][j][2]), "+f"(acc[0][j][3])
                    : "r"(fui(fa0.x)), "r"(fui(fa0.y)), "r"(fui(fa0.z)), "r"(fui(fa0.w)),
                      "r"(b0), "r"(b1));
                asm volatile(
                    "mma.sync.aligned.m16n8k8.row.col.f32.tf32.tf32.f32 "
                    "{%0,%1,%2,%3}, {%4,%5,%6,%7}, {%8,%9}, {%0,%1,%2,%3};"
                    : "+f"(acc[1][j][0]), "+f"(acc[1][j][1]),
                      "+f"(acc[1][j][2]), "+f"(acc[1][j][3])
                    : "r"(fui(fa1.x)), "r"(fui(fa1.y)), "r"(fui(fa1.z)), "r"(fui(fa1.w)),
                      "r"(b0), "r"(b1));
            }
        }

        if (hasNext) commit(cur ^ 1);
        __syncthreads();
    }

    // ---- epilogue: bias add, store raw, fused BN stats ----
#pragma unroll
    for (int j = 0; j < 4; j++) {
        int c = col0 + wn + 8 * j + 2 * qc;
        float bx = bias[c], by = bias[c + 1];
#pragma unroll
        for (int i = 0; i < 2; i++) {
            acc[i][j][0] += bx; acc[i][j][1] += by;
            acc[i][j][2] += bx; acc[i][j][3] += by;
        }
    }
#pragma unroll
    for (int i = 0; i < 2; i++) {
        int r = row0 + wm + 16 * i + qr;
#pragma unroll
        for (int j = 0; j < 4; j++) {
            int c = col0 + wn + 8 * j + 2 * qc;
            if (r < M)
                *(float2*)(C + (size_t)r * N + c) = make_float2(acc[i][j][0], acc[i][j][1]);
            if (r + 8 < M)
                *(float2*)(C + (size_t)(r + 8) * N + c) = make_float2(acc[i][j][2], acc[i][j][3]);
        }
    }
#pragma unroll
    for (int j = 0; j < 4; j++) {
        float s0 = 0.f, q0 = 0.f, s1 = 0.f, q1 = 0.f;
#pragma unroll
        for (int i = 0; i < 2; i++) {
            int r = row0 + wm + 16 * i + qr;
            if (r < M) {
                s0 += acc[i][j][0]; q0 += acc[i][j][0] * acc[i][j][0];
                s1 += acc[i][j][1]; q1 += acc[i][j][1] * acc[i][j][1];
            }
            if (r + 8 < M) {
                s0 += acc[i][j][2]; q0 += acc[i][j][2] * acc[i][j][2];
                s1 += acc[i][j][3]; q1 += acc[i][j][3] * acc[i][j][3];
            }
        }
#pragma unroll
        for (int off = 4; off < 32; off <<= 1) {
            s0 += __shfl_xor_sync(0xffffffff, s0, off);
            q0 += __shfl_xor_sync(0xffffffff, q0, off);
            s1 += __shfl_xor_sync(0xffffffff, s1, off);
            q1 += __shfl_xor_sync(0xffffffff, q1, off);
        }
        if (qr == 0) {
            int c = col0 + wn + 8 * j + 2 * qc;
            atomicAdd(&g_sums[soff + c], s0);
            atomicAdd(&g_ssqs[soff + c], q0);
            atomicAdd(&g_sums[soff + c + 1], s1);
            atomicAdd(&g_ssqs[soff + c + 1], q1);
        }
    }
}

// ---------------- propagation (ELL by dst; unroll x2 dual accumulators) ----------------
__global__ __launch_bounds__(128, 8) void k_prop(int hid, int outid, int F, int coff) {
    const float* h = buf(hid);
    float* out = buf(outid);
    int node = blockIdx.x;
    int t = threadIdx.x;
    int cnt = g_cnt[node];
    int base = node * ELLW;
    float4 sc = make_float4(1.f, 1.f, 1.f, 1.f), sh = make_float4(0.f, 0.f, 0.f, 0.f);
    bool useC = coff >= 0;
    if (useC) {
        sc = *(const float4*)(g_bnsc + coff + t * 4);
        sh = *(const float4*)(g_bnsh + coff + t * 4);
    }
    float4 acc = make_float4(0.f, 0.f, 0.f, 0.f);
    float4 acc2 = make_float4(0.f, 0.f, 0.f, 0.f);
    int e = 0;
    for (; e + 2 <= cnt; e += 2) {
        int s0 = g_ell_src[base + e];
        int s1 = g_ell_src[base + e + 1];
        float w0 = g_ell_w[base + e];
        float w1 = g_ell_w[base + e + 1];
        float4 v0 = *(const float4*)(h + (size_t)s0 * F + t * 4);
        float4 v1 = *(const float4*)(h + (size_t)s1 * F + t * 4);
        if (useC) {
            v0.x = fmaxf(fmaf(v0.x, sc.x, sh.x), 0.f);
            v0.y = fmaxf(fmaf(v0.y, sc.y, sh.y), 0.f);
            v0.z = fmaxf(fmaf(v0.z, sc.z, sh.z), 0.f);
            v0.w = fmaxf(fmaf(v0.w, sc.w, sh.w), 0.f);
            v1.x = fmaxf(fmaf(v1.x, sc.x, sh.x), 0.f);
            v1.y = fmaxf(fmaf(v1.y, sc.y, sh.y), 0.f);
            v1.z = fmaxf(fmaf(v1.z, sc.z, sh.z), 0.f);
            v1.w = fmaxf(fmaf(v1.w, sc.w, sh.w), 0.f);
        }
        acc.x += w0 * v0.x; acc.y += w0 * v0.y; acc.z += w0 * v0.z; acc.w += w0 * v0.w;
        acc2.x += w1 * v1.x; acc2.y += w1 * v1.y; acc2.z += w1 * v1.z; acc2.w += w1 * v1.w;
    }
    if (e < cnt) {
        int s0 = g_ell_src[base + e];
        float w0 = g_ell_w[base + e];
        float4 v0 = *(const float4*)(h + (size_t)s0 * F + t * 4);
        if (useC) {
            v0.x = fmaxf(fmaf(v0.x, sc.x, sh.x), 0.f);
            v0.y = fmaxf(fmaf(v0.y, sc.y, sh.y), 0.f);
            v0.z = fmaxf(fmaf(v0.z, sc.z, sh.z), 0.f);
            v0.w = fmaxf(fmaf(v0.w, sc.w, sh.w), 0.f);
        }
        acc.x += w0 * v0.x; acc.y += w0 * v0.y; acc.z += w0 * v0.z; acc.w += w0 * v0.w;
    }
    acc.x += acc2.x; acc.y += acc2.y; acc.z += acc2.z; acc.w += acc2.w;
    *(float4*)(out + (size_t)node * F + t * 4) = acc;
}

__global__ __launch_bounds__(128, 8) void k_prop_cheb(int hid, int subid, int outid, int F, int subcoff) {
    const float* h = buf(hid);
    const float* sub = buf(subid);
    float* out = buf(outid);
    int node = blockIdx.x;
    int t = threadIdx.x;
    int cnt = g_cnt[node];
    int base = node * ELLW;
    float4 acc = make_float4(0.f, 0.f, 0.f, 0.f);
    float4 acc2 = make_float4(0.f, 0.f, 0.f, 0.f);
    int e = 0;
    for (; e + 2 <= cnt; e += 2) {
        int s0 = g_ell_src[base + e];
        int s1 = g_ell_src[base + e + 1];
        float w0 = g_ell_w[base + e];
        float w1 = g_ell_w[base + e + 1];
        float4 v0 = *(const float4*)(h + (size_t)s0 * F + t * 4);
        float4 v1 = *(const float4*)(h + (size_t)s1 * F + t * 4);
        acc.x += w0 * v0.x; acc.y += w0 * v0.y; acc.z += w0 * v0.z; acc.w += w0 * v0.w;
        acc2.x += w1 * v1.x; acc2.y += w1 * v1.y; acc2.z += w1 * v1.z; acc2.w += w1 * v1.w;
    }
    if (e < cnt) {
        int s0 = g_ell_src[base + e];
        float w0 = g_ell_w[base + e];
        float4 v0 = *(const float4*)(h + (size_t)s0 * F + t * 4);
        acc.x += w0 * v0.x; acc.y += w0 * v0.y; acc.z += w0 * v0.z; acc.w += w0 * v0.w;
    }
    acc.x += acc2.x; acc.y += acc2.y; acc.z += acc2.z; acc.w += acc2.w;
    float4 sc = *(const float4*)(g_bnsc + subcoff + t * 4);
    float4 sh = *(const float4*)(g_bnsh + subcoff + t * 4);
    float4 sv = *(const float4*)(sub + (size_t)node * F + t * 4);
    sv.x = fmaxf(fmaf(sv.x, sc.x, sh.x), 0.f);
    sv.y = fmaxf(fmaf(sv.y, sc.y, sh.y), 0.f);
    sv.z = fmaxf(fmaf(sv.z, sc.z, sh.z), 0.f);
    sv.w = fmaxf(fmaf(sv.w, sc.w, sh.w), 0.f);
    float4 r;
    r.x = 2.0f * acc.x - sv.x;
    r.y = 2.0f * acc.y - sv.y;
    r.z = 2.0f * acc.z - sv.z;
    r.w = 2.0f * acc.w - sv.w;
    *(float4*)(out + (size_t)node * F + t * 4) = r;
}

// ---------------- fc (bn3 on load; 128 -> 6) + log_softmax ----------------
__global__ void k_fc(const float* __restrict__ W,
                     const float* __restrict__ bias, float* __restrict__ out, int n) {
    const float* h = g_y3;
    int gtid = blockIdx.x * blockDim.x + threadIdx.x;
    int node = gtid >> 5;
    int lane = gtid & 31;
    if (node >= n) return;
    float hv[4];
#pragma unroll
    for (int k = 0; k < 4; k++) {
        int col = lane + 32 * k;
        float raw = h[(size_t)node * 128 + col];
        hv[k] = fmaf(raw, g_bnsc[768 + col], g_bnsh[768 + col]);
    }
    float logit[6];
#pragma unroll
    for (int j = 0; j < 6; j++) {
        float s = 0.0f;
#pragma unroll
        for (int k = 0; k < 4; k++) s += hv[k] * W[(lane + 32 * k) * 6 + j];
#pragma unroll
        for (int o = 16; o > 0; o >>= 1) s += __shfl_xor_sync(0xffffffff, s, o);
        logit[j] = s + bias[j];
    }
    if (lane == 0) {
        float mx = logit[0];
#pragma unroll
        for (int j = 1; j < 6; j++) mx = fmaxf(mx, logit[j]);
        float se = 0.0f;
#pragma unroll
        for (int j = 0; j < 6; j++) se += expf(logit[j] - mx);
        float lse = mx + logf(se);
#pragma unroll
        for (int j = 0; j < 6; j++) out[(size_t)node * 6 + j] = logit[j] - lse;
    }
}

// ---------------- launch ----------------
extern "C" void kernel_launch(void* const* d_in, const int* in_sizes, int n_in,
                              void* d_out, int out_size) {
    const float* x    = (const float*)d_in[0];
    const int*   ei   = (const int*)d_in[1];
    const float* ea   = (const float*)d_in[2];
    const float* W1_0 = (const float*)d_in[3];
    const float* b1   = (const float*)d_in[4];
    const float* g1   = (const float*)d_in[5];
    const float* be1  = (const float*)d_in[6];
    const float* W2_0 = (const float*)d_in[7];
    const float* W2_1 = (const float*)d_in[8];
    const float* b2   = (const float*)d_in[9];
    const float* g2   = (const float*)d_in[10];
    const float* be2  = (const float*)d_in[11];
    const float* W3_0 = (const float*)d_in[12];
    const float* W3_1 = (const float*)d_in[13];
    const float* W3_2 = (const float*)d_in[14];
    const float* b3   = (const float*)d_in[15];
    const float* g3   = (const float*)d_in[16];
    const float* be3  = (const float*)d_in[17];
    const float* fcW  = (const float*)d_in[18];
    const float* fcb  = (const float*)d_in[19];
    float* out = (float*)d_out;

    // ---- graph normalization + ELL build ----
    k_init_graph<<<CEILDIV(NN, 256), 256>>>();
    k_deg<<<CEILDIV(EE, 256), 256>>>(ei, ea);
    k_norm_push<<<CEILDIV(EE, 256), 256>>>(ei, ea);

    const int GY = CEILDIV(NN, BMT);   // 157

    // ---- layer 1 ----
    gemm_tf32<<<dim3(512 / BNT, GY), 256>>>(
        x, 0, 0, 0, W1_0, nullptr, nullptr, b1, 1, NN, 512, 768, 1, 0, -1, -1, -1);
    k_bn_coef<<<1, 512>>>(g1, be1, NN, 512, 0);

    // ---- layer 2 ----
    k_prop<<<NN, 128>>>(1, 2, 512, 0);
    gemm_tf32<<<dim3(256 / BNT, GY), 256>>>(
        nullptr, 1, 2, 0, W2_0, W2_1, nullptr, b2, 3, NN, 256, 512, 2, 512, 0, -1, -1);
    k_bn_coef<<<1, 256>>>(g2, be2, NN, 256, 512);

    // ---- layer 3 ----
    k_prop<<<NN, 64>>>(3, 4, 256, 512);
    k_prop_cheb<<<NN, 64>>>(4, 3, 5, 256, 512);
    gemm_tf32<<<dim3(128 / BNT, GY), 256>>>(
        nullptr, 3, 4, 5, W3_0, W3_1, W3_2, b3, 6, NN, 128, 256, 3, 768, 512, -1, -1);
    k_bn_coef<<<1, 128>>>(g3, be3, NN, 128, 768);

    // ---- fc (bn3 fused) + log_softmax ----
    k_fc<<<CEILDIV(NN * 32, 256), 256>>>(fcW, fcb, out, NN);
}

// round 13
// speedup vs baseline: 1.4541x; 1.0631x over previous
#include <cuda_runtime.h>

#define NN 10000
#define EE 160000
#define EPS 1e-5f
#define ELLW 64
#define CEILDIV(a,b) (((a)+(b)-1)/(b))

// ---------------- scratch (static device globals; no allocation) ----------------
__device__ __align__(16) float g_deg[NN];
__device__ __align__(16) int   g_cnt[NN];
__device__ __align__(16) int   g_ell_src[NN * ELLW];
__device__ __align__(16) float g_ell_w[NN * ELLW];
__device__ __align__(16) float g_y1[NN * 512];
__device__ __align__(16) float g_t1[NN * 512];
__device__ __align__(16) float g_y2[NN * 256];
__device__ __align__(16) float g_p2[NN * 256];
__device__ __align__(16) float g_tx2[NN * 256];
__device__ __align__(16) float g_y3[NN * 128];
__device__ __align__(16) float g_tB1[768 * 512];    // tf32-preconverted weights (K-concat)
__device__ __align__(16) float g_tB2[1024 * 256];
__device__ __align__(16) float g_tB3[768 * 128];
__device__ __align__(16) float g_sums[896];
__device__ __align__(16) float g_ssqs[896];
__device__ __align__(16) float g_bnsc[896];
__device__ __align__(16) float g_bnsh[896];

__device__ __forceinline__ float* buf(int id) {
    switch (id) {
        case 1: return g_y1;
        case 2: return g_t1;
        case 3: return g_y2;
        case 4: return g_p2;
        case 5: return g_tx2;
        case 6: return g_y3;
        case 7: return g_tB1;
        case 8: return g_tB2;
        case 9: return g_tB3;
    }
    return nullptr;
}

__device__ __forceinline__ unsigned f2tf(float x) {
    unsigned u;
    asm("cvt.rna.tf32.f32 %0, %1;" : "=r"(u) : "f"(x));
    return u;
}
__device__ __forceinline__ unsigned fui(float x) { return __float_as_uint(x); }

// ---------------- graph build (ELL by dst) ----------------
__global__ void k_init_graph() {
    int i = blockIdx.x * blockDim.x + threadIdx.x;
    if (i < NN) { g_deg[i] = 0.0f; g_cnt[i] = 0; }
    if (i < 896) { g_sums[i] = 0.0f; g_ssqs[i] = 0.0f; }
}
__global__ void k_deg(const int* __restrict__ ei, const float* __restrict__ ea) {
    int e = blockIdx.x * blockDim.x + threadIdx.x;
    if (e >= EE) return;
    atomicAdd(&g_deg[ei[e]], ea[e]);
}
__global__ void k_norm_push(const int* __restrict__ ei, const float* __restrict__ ea) {
    int e = blockIdx.x * blockDim.x + threadIdx.x;
    if (e >= EE) return;
    int s = ei[e];
    int d = ei[EE + e];
    float ds = g_deg[s], dd = g_deg[d];
    float is = (ds > 0.0f) ? rsqrtf(ds) : 0.0f;
    float id = (dd > 0.0f) ? rsqrtf(dd) : 0.0f;
    float w = -is * ea[e] * id;
    int pos = atomicAdd(&g_cnt[d], 1);
    g_ell_src[d * ELLW + pos] = s;
    g_ell_w[d * ELLW + pos] = w;
}

// ---------------- BN coefficients ----------------
__global__ void k_bn_coef(const float* __restrict__ gamma, const float* __restrict__ beta,
                          int n, int F, int soff) {
    int f = threadIdx.x;
    if (f >= F) return;
    float inv_n = 1.0f / (float)n;
    float mu = g_sums[soff + f] * inv_n;
    float var = g_ssqs[soff + f] * inv_n - mu * mu;
    float sc = gamma[f] * rsqrtf(var + EPS);
    g_bnsc[soff + f] = sc;
    g_bnsh[soff + f] = beta[f] - mu * sc;
}

// ---------------- one-time B tf32 pre-convert (+K-concat) ----------------
__global__ void k_cvtB(const float* __restrict__ B0, const float* __restrict__ B1,
                       const float* __restrict__ B2, int Kseg, int N, int K, int dstid) {
    int idx = blockIdx.x * blockDim.x + threadIdx.x;
    if (idx >= K * N) return;
    int row = idx / N;
    int col = idx - row * N;
    int seg = row / Kseg;
    int rloc = row - seg * Kseg;
    const float* B = (seg == 0) ? B0 : (seg == 1) ? B1 : B2;
    buf(dstid)[idx] = __uint_as_float(f2tf(B[rloc * N + col]));
}

// ---------------- tf32 GEMM: BM=64, BN=128, BKT=16, fragment-major A smem,
// pre-converted concatenated B (no cvt, no div in main loop) ----------------
#define BMT 64
#define BNT 128
#define BKT 16
#define NF 4
#define A_STAGE (2 * NF * 128)   // 1024 floats
#define BPAD 136

__global__ __launch_bounds__(256, 3) void gemm_tf32(
    const float* __restrict__ Aext, int aid0, int aid1, int aid2, int tBid,
    const float* __restrict__ bias, int Cid,
    int M, int N, int Kseg, int segs, int soff, int coff0)
{
    __shared__ __align__(16) float As[2][A_STAGE];
    __shared__ __align__(16) float Bs[2][BKT][BPAD];

    const float* Ap[3];
    Ap[0] = Aext ? Aext : buf(aid0);
    Ap[1] = buf(aid1);
    Ap[2] = buf(aid2);
    float* C = buf(Cid);

    const int tid = threadIdx.x;
    const int lane = tid & 31;
    const int warp = tid >> 5;
    const int qr = lane >> 2;
    const int qc = lane & 3;
    const int wm = (warp & 1) * 32;
    const int ms0 = (warp & 1) * 2;
    const int wn = (warp >> 1) * 32;

    const int row0 = blockIdx.y * BMT;
    const int col0 = blockIdx.x * BNT;

    // A loader: one float4 per thread: row=tid/4, k=(tid&3)*4
    const int arow = tid >> 2;
    const int ak = (tid & 3) << 2;
    const bool avalid = (row0 + arow) < M;
    const int wr = arow & 15;
    const int wms = arow >> 4;
    const int wkh = ak >> 3;
    const int wkb = (ak >> 2) & 1;
    const int xsw = ((wr >> 1) & 3) << 2;
    const int awbase = (wkh * NF + wms) * 128 + ((wr & 7) << 4) + (wr >> 3) + (wkb << 1);

    // A fragment read base
    const int rpos = (qr << 2) + (qc ^ ((qr >> 1) & 3));
    const int ardbase = ms0 * 128 + (rpos << 2);

    // B loader
    const int brow = tid >> 5;
    const int bcol = (tid & 31) << 2;

    float acc[2][4][4];
#pragma unroll
    for (int i = 0; i < 2; i++)
#pragma unroll
        for (int j = 0; j < 4; j++)
#pragma unroll
            for (int e = 0; e < 4; e++) acc[i][j][e] = 0.0f;

    // pointer-walk state (no division in main loop)
    const size_t aoff = (size_t)(row0 + arow) * Kseg + ak;
    const float* pA = Ap[0] + aoff;
    const float* psc = g_bnsc + (coff0 >= 0 ? coff0 : 0) + ak;
    const float* psh = g_bnsh + (coff0 >= 0 ? coff0 : 0) + ak;
    const float* pB = buf(tBid) + (size_t)brow * N + col0 + bcol;
    const int bstep = BKT * N;
    int segi = 0, kcnt = 0;
    const int kperseg = Kseg / BKT;
    const int niter = kperseg * segs;

    float4 rA, rB[2];
    auto fetch = [&]() {
        rA = make_float4(0.f, 0.f, 0.f, 0.f);
        if (avalid) rA = *(const float4*)pA;
        if (coff0 >= 0 && segi == 0) {
            float4 sc = *(const float4*)psc;
            float4 sh = *(const float4*)psh;
            rA.x = fmaxf(fmaf(rA.x, sc.x, sh.x), 0.f);
            rA.y = fmaxf(fmaf(rA.y, sc.y, sh.y), 0.f);
            rA.z = fmaxf(fmaf(rA.z, sc.z, sh.z), 0.f);
            rA.w = fmaxf(fmaf(rA.w, sc.w, sh.w), 0.f);
        }
        rB[0] = *(const float4*)pB;
        rB[1] = *(const float4*)(pB + (size_t)8 * N);
    };
    auto advance = [&]() {
        kcnt++;
        if (kcnt == kperseg) {
            kcnt = 0; segi++;
            if (segi < segs) pA = Ap[segi] + aoff;
        } else {
            pA += BKT;
        }
        psc += BKT; psh += BKT;
        pB += bstep;
    };
    auto commit = [&](int s) {
        float* Aw = As[s];
        Aw[awbase + ((0 << 2) ^ xsw)] = __uint_as_float(f2tf(rA.x));
        Aw[awbase + ((1 << 2) ^ xsw)] = __uint_as_float(f2tf(rA.y));
        Aw[awbase + ((2 << 2) ^ xsw)] = __uint_as_float(f2tf(rA.z));
        Aw[awbase + ((3 << 2) ^ xsw)] = __uint_as_float(f2tf(rA.w));
        *(float4*)&Bs[s][brow][bcol] = rB[0];       // already tf32 bits
        *(float4*)&Bs[s][brow + 8][bcol] = rB[1];
    };

    fetch();
    advance();
    commit(0);
    __syncthreads();

    int cur = 0;
    for (int it = 0; it < niter; it++, cur ^= 1) {
        const bool hasNext = (it + 1) < niter;
        if (hasNext) { fetch(); advance(); }

        const float* Ac = As[cur];
        const float* Bc = &Bs[cur][0][0];
#pragma unroll
        for (int kh = 0; kh < 2; kh++) {
            const float* Af = Ac + kh * (NF * 128) + ardbase;
            float4 fa0 = *(const float4*)(Af);
            float4 fa1 = *(const float4*)(Af + 128);
            const float* Bk0 = Bc + (kh * 8 + qc) * BPAD + wn + qr;
            const float* Bk1 = Bk0 + 4 * BPAD;
#pragma unroll
            for (int j = 0; j < 4; j++) {
                unsigned b0 = fui(Bk0[8 * j]);
                unsigned b1 = fui(Bk1[8 * j]);
                asm volatile(
                    "mma.sync.aligned.m16n8k8.row.col.f32.tf32.tf32.f32 "
                    "{%0,%1,%2,%3}, {%4,%5,%6,%7}, {%8,%9}, {%0,%1,%2,%3};"
                    : "+f"(acc[0][j][0]), "+f"(acc[0][j][1]),
                      "+f"(acc[0][j][2]), "+f"(acc[0][j][3])
                    : "r"(fui(fa0.x)), "r"(fui(fa0.y)), "r"(fui(fa0.z)), "r"(fui(fa0.w)),
                      "r"(b0), "r"(b1));
                asm volatile(
                    "mma.sync.aligned.m16n8k8.row.col.f32.tf32.tf32.f32 "
                    "{%0,%1,%2,%3}, {%4,%5,%6,%7}, {%8,%9}, {%0,%1,%2,%3};"
                    : "+f"(acc[1][j][0]), "+f"(acc[1][j][1]),
                      "+f"(acc[1][j][2]), "+f"(acc[1][j][3])
                    : "r"(fui(fa1.x)), "r"(fui(fa1.y)), "r"(fui(fa1.z)), "r"(fui(fa1.w)),
                      "r"(b0), "r"(b1));
            }
        }

        if (hasNext) commit(cur ^ 1);
        __syncthreads();
    }

    // ---- epilogue: bias add, store raw, fused BN stats ----
#pragma unroll
    for (int j = 0; j < 4; j++) {
        int c = col0 + wn + 8 * j + 2 * qc;
        float bx = bias[c], by = bias[c + 1];
#pragma unroll
        for (int i = 0; i < 2; i++) {
            acc[i][j][0] += bx; acc[i][j][1] += by;
            acc[i][j][2] += bx; acc[i][j][3] += by;
        }
    }
#pragma unroll
    for (int i = 0; i < 2; i++) {
        int r = row0 + wm + 16 * i + qr;
#pragma unroll
        for (int j = 0; j < 4; j++) {
            int c = col0 + wn + 8 * j + 2 * qc;
            if (r < M)
                *(float2*)(C + (size_t)r * N + c) = make_float2(acc[i][j][0], acc[i][j][1]);
            if (r + 8 < M)
                *(float2*)(C + (size_t)(r + 8) * N + c) = make_float2(acc[i][j][2], acc[i][j][3]);
        }
    }
#pragma unroll
    for (int j = 0; j < 4; j++) {
        float s0 = 0.f, q0 = 0.f, s1 = 0.f, q1 = 0.f;
#pragma unroll
        for (int i = 0; i < 2; i++) {
            int r = row0 + wm + 16 * i + qr;
            if (r < M) {
                s0 += acc[i][j][0]; q0 += acc[i][j][0] * acc[i][j][0];
                s1 += acc[i][j][1]; q1 += acc[i][j][1] * acc[i][j][1];
            }
            if (r + 8 < M) {
                s0 += acc[i][j][2]; q0 += acc[i][j][2] * acc[i][j][2];
                s1 += acc[i][j][3]; q1 += acc[i][j][3] * acc[i][j][3];
            }
        }
#pragma unroll
        for (int off = 4; off < 32; off <<= 1) {
            s0 += __shfl_xor_sync(0xffffffff, s0, off);
            q0 += __shfl_xor_sync(0xffffffff, q0, off);
            s1 += __shfl_xor_sync(0xffffffff, s1, off);
            q1 += __shfl_xor_sync(0xffffffff, q1, off);
        }
        if (qr == 0) {
            int c = col0 + wn + 8 * j + 2 * qc;
            atomicAdd(&g_sums[soff + c], s0);
            atomicAdd(&g_ssqs[soff + c], q0);
            atomicAdd(&g_sums[soff + c + 1], s1);
            atomicAdd(&g_ssqs[soff + c + 1], q1);
        }
    }
}

// ---------------- propagation (ELL by dst; BN+ReLU applied to gathered h) — R8 form ----------------
__global__ void k_prop(int hid, int outid, int F, int coff) {
    const float* h = buf(hid);
    float* out = buf(outid);
    int node = blockIdx.x;
    int t = threadIdx.x;
    int cnt = g_cnt[node];
    int base = node * ELLW;
    float4 sc = make_float4(1.f, 1.f, 1.f, 1.f), sh = make_float4(0.f, 0.f, 0.f, 0.f);
    bool useC = coff >= 0;
    if (useC) {
        sc = *(const float4*)(g_bnsc + coff + t * 4);
        sh = *(const float4*)(g_bnsh + coff + t * 4);
    }
    float4 acc = make_float4(0.f, 0.f, 0.f, 0.f);
    for (int e = 0; e < cnt; e++) {
        int s = g_ell_src[base + e];
        float w = g_ell_w[base + e];
        float4 v = *(const float4*)(h + (size_t)s * F + t * 4);
        if (useC) {
            v.x = fmaxf(fmaf(v.x, sc.x, sh.x), 0.f);
            v.y = fmaxf(fmaf(v.y, sc.y, sh.y), 0.f);
            v.z = fmaxf(fmaf(v.z, sc.z, sh.z), 0.f);
            v.w = fmaxf(fmaf(v.w, sc.w, sh.w), 0.f);
        }
        acc.x += w * v.x; acc.y += w * v.y; acc.z += w * v.z; acc.w += w * v.w;
    }
    *(float4*)(out + (size_t)node * F + t * 4) = acc;
}

__global__ void k_prop_cheb(int hid, int subid, int outid, int F, int subcoff) {
    const float* h = buf(hid);
    const float* sub = buf(subid);
    float* out = buf(outid);
    int node = blockIdx.x;
    int t = threadIdx.x;
    int cnt = g_cnt[node];
    int base = node * ELLW;
    float4 acc = make_float4(0.f, 0.f, 0.f, 0.f);
    for (int e = 0; e < cnt; e++) {
        int s = g_ell_src[base + e];
        float w = g_ell_w[base + e];
        float4 v = *(const float4*)(h + (size_t)s * F + t * 4);
        acc.x += w * v.x; acc.y += w * v.y; acc.z += w * v.z; acc.w += w * v.w;
    }
    float4 sc = *(const float4*)(g_bnsc + subcoff + t * 4);
    float4 sh = *(const float4*)(g_bnsh + subcoff + t * 4);
    float4 sv = *(const float4*)(sub + (size_t)node * F + t * 4);
    sv.x = fmaxf(fmaf(sv.x, sc.x, sh.x), 0.f);
    sv.y = fmaxf(fmaf(sv.y, sc.y, sh.y), 0.f);
    sv.z = fmaxf(fmaf(sv.z, sc.z, sh.z), 0.f);
    sv.w = fmaxf(fmaf(sv.w, sc.w, sh.w), 0.f);
    float4 r;
    r.x = 2.0f * acc.x - sv.x;
    r.y = 2.0f * acc.y - sv.y;
    r.z = 2.0f * acc.z - sv.z;
    r.w = 2.0f * acc.w - sv.w;
    *(float4*)(out + (size_t)node * F + t * 4) = r;
}

// ---------------- fc (bn3 on load; 128 -> 6) + log_softmax ----------------
__global__ void k_fc(const float* __restrict__ W,
                     const float* __restrict__ bias, float* __restrict__ out, int n) {
    const float* h = g_y3;
    int gtid = blockIdx.x * blockDim.x + threadIdx.x;
    int node = gtid >> 5;
    int lane = gtid & 31;
    if (node >= n) return;
    float hv[4];
#pragma unroll
    for (int k = 0; k < 4; k++) {
        int col = lane + 32 * k;
        float raw = h[(size_t)node * 128 + col];
        hv[k] = fmaf(raw, g_bnsc[768 + col], g_bnsh[768 + col]);
    }
    float logit[6];
#pragma unroll
    for (int j = 0; j < 6; j++) {
        float s = 0.0f;
#pragma unroll
        for (int k = 0; k < 4; k++) s += hv[k] * W[(lane + 32 * k) * 6 + j];
#pragma unroll
        for (int o = 16; o > 0; o >>= 1) s += __shfl_xor_sync(0xffffffff, s, o);
        logit[j] = s + bias[j];
    }
    if (lane == 0) {
        float mx = logit[0];
#pragma unroll
        for (int j = 1; j < 6; j++) mx = fmaxf(mx, logit[j]);
        float se = 0.0f;
#pragma unroll
        for (int j = 0; j < 6; j++) se += expf(logit[j] - mx);
        float lse = mx + logf(se);
#pragma unroll
        for (int j = 0; j < 6; j++) out[(size_t)node * 6 + j] = logit[j] - lse;
    }
}

// ---------------- launch ----------------
extern "C" void kernel_launch(void* const* d_in, const int* in_sizes, int n_in,
                              void* d_out, int out_size) {
    const float* x    = (const float*)d_in[0];
    const int*   ei   = (const int*)d_in[1];
    const float* ea   = (const float*)d_in[2];
    const float* W1_0 = (const float*)d_in[3];
    const float* b1   = (const float*)d_in[4];
    const float* g1   = (const float*)d_in[5];
    const float* be1  = (const float*)d_in[6];
    const float* W2_0 = (const float*)d_in[7];
    const float* W2_1 = (const float*)d_in[8];
    const float* b2   = (const float*)d_in[9];
    const float* g2   = (const float*)d_in[10];
    const float* be2  = (const float*)d_in[11];
    const float* W3_0 = (const float*)d_in[12];
    const float* W3_1 = (const float*)d_in[13];
    const float* W3_2 = (const float*)d_in[14];
    const float* b3   = (const float*)d_in[15];
    const float* g3   = (const float*)d_in[16];
    const float* be3  = (const float*)d_in[17];
    const float* fcW  = (const float*)d_in[18];
    const float* fcb  = (const float*)d_in[19];
    float* out = (float*)d_out;

    // ---- one-time B tf32 pre-convert ----
    k_cvtB<<<CEILDIV(768 * 512, 256), 256>>>(W1_0, nullptr, nullptr, 768, 512, 768, 7);
    k_cvtB<<<CEILDIV(1024 * 256, 256), 256>>>(W2_0, W2_1, nullptr, 512, 256, 1024, 8);
    k_cvtB<<<CEILDIV(768 * 128, 256), 256>>>(W3_0, W3_1, W3_2, 256, 128, 768, 9);

    // ---- graph normalization + ELL build ----
    k_init_graph<<<CEILDIV(NN, 256), 256>>>();
    k_deg<<<CEILDIV(EE, 256), 256>>>(ei, ea);
    k_norm_push<<<CEILDIV(EE, 256), 256>>>(ei, ea);

    const int GY = CEILDIV(NN, BMT);   // 157

    // ---- layer 1 ----
    gemm_tf32<<<dim3(512 / BNT, GY), 256>>>(
        x, 0, 0, 0, 7, b1, 1, NN, 512, 768, 1, 0, -1);
    k_bn_coef<<<1, 512>>>(g1, be1, NN, 512, 0);

    // ---- layer 2 ----
    k_prop<<<NN, 128>>>(1, 2, 512, 0);
    gemm_tf32<<<dim3(256 / BNT, GY), 256>>>(
        nullptr, 1, 2, 0, 8, b2, 3, NN, 256, 512, 2, 512, 0);
    k_bn_coef<<<1, 256>>>(g2, be2, NN, 256, 512);

    // ---- layer 3 ----
    k_prop<<<NN, 64>>>(3, 4, 256, 512);
    k_prop_cheb<<<NN, 64>>>(4, 3, 5, 256, 512);
    gemm_tf32<<<dim3(128 / BNT, GY), 256>>>(
        nullptr, 3, 4, 5, 9, b3, 6, NN, 128, 256, 3, 768, 512);
    k_bn_coef<<<1, 128>>>(g3, be3, NN, 128, 768);

    // ---- fc (bn3 fused) + log_softmax ----
    k_fc<<<CEILDIV(NN * 32, 256), 256>>>(fcW, fcb, out, NN);
}